// round 1
// baseline (speedup 1.0000x reference)
#include <cuda_runtime.h>

#define B_   256
#define T_   256
#define EMB_ 384
#define H_   64
#define M_   (B_*T_)

// Scratch for q,k,v projections: [3][B*T][H]
__device__ float g_qkv[3][(size_t)M_ * H_];

// ---------------------------------------------------------------------------
// Kernel 1: QKV projection GEMM.  out[z][m][n] = sum_k x[m][k] * W_z[k][n]
// BM=128, BN=64, BK=16, 256 threads, 8x4 microtile per thread.
// ---------------------------------------------------------------------------
__global__ __launch_bounds__(256) void qkv_gemm(
    const float* __restrict__ x,
    const float* __restrict__ Wq,
    const float* __restrict__ Wk,
    const float* __restrict__ Wv)
{
    __shared__ float As[16][132];   // [kk][row], padded to dodge bank conflicts
    __shared__ float Bs[16][64];    // [kk][col]

    const float* W = (blockIdx.z == 0) ? Wq : (blockIdx.z == 1) ? Wk : Wv;
    float* out = g_qkv[blockIdx.z];

    const int m0  = blockIdx.y * 128;
    const int tid = threadIdx.x;
    const int tx  = tid & 15;        // 0..15 -> 4 output cols each
    const int ty  = tid >> 4;        // 0..15 -> 8 output rows each

    float c[8][4] = {};

    for (int k0 = 0; k0 < EMB_; k0 += 16) {
        // Load A tile: 128 rows x 16 k -> 512 float4 loads, 2 per thread
        #pragma unroll
        for (int f = tid; f < 512; f += 256) {
            int row = f >> 2;
            int kc  = (f & 3) * 4;
            float4 t = *(const float4*)&x[(size_t)(m0 + row) * EMB_ + k0 + kc];
            As[kc + 0][row] = t.x;
            As[kc + 1][row] = t.y;
            As[kc + 2][row] = t.z;
            As[kc + 3][row] = t.w;
        }
        // Load B tile: 16 k x 64 cols -> 256 float4, 1 per thread
        {
            int row = tid >> 4;
            int col = (tid & 15) * 4;
            *(float4*)&Bs[row][col] = *(const float4*)&W[(size_t)(k0 + row) * H_ + col];
        }
        __syncthreads();

        #pragma unroll
        for (int kk = 0; kk < 16; kk++) {
            float a[8];
            #pragma unroll
            for (int r = 0; r < 8; r++) a[r] = As[kk][ty * 8 + r];
            float4 b = *(float4*)&Bs[kk][tx * 4];
            #pragma unroll
            for (int r = 0; r < 8; r++) {
                c[r][0] += a[r] * b.x;
                c[r][1] += a[r] * b.y;
                c[r][2] += a[r] * b.z;
                c[r][3] += a[r] * b.w;
            }
        }
        __syncthreads();
    }

    #pragma unroll
    for (int r = 0; r < 8; r++) {
        float4 o = make_float4(c[r][0], c[r][1], c[r][2], c[r][3]);
        *(float4*)&out[(size_t)(m0 + ty * 8 + r) * H_ + tx * 4] = o;
    }
}

// ---------------------------------------------------------------------------
// Kernel 2: causal attention, one CTA per batch element.
// 512 threads = 16 warps; warp w owns rows t = w, w+16, ...
// ---------------------------------------------------------------------------
#define NW 16

struct AttnSmem {
    float  kT[H_][T_];        // K transposed: kT[h][j] = k[j][h]   (64 KB)
    float2 vs[T_][H_ / 2];    // V interleaved as float2            (64 KB)
    float  wbuf[NW][T_];      // per-warp softmax weights           (16 KB)
    float  qrow[NW][H_];      // per-warp current q row             ( 4 KB)
};

__global__ __launch_bounds__(512) void attn_kernel(float* __restrict__ out)
{
    extern __shared__ char smem_raw[];
    AttnSmem* s = (AttnSmem*)smem_raw;

    const int b    = blockIdx.x;
    const int tid  = threadIdx.x;
    const int lane = tid & 31;
    const int w    = tid >> 5;

    const float* q = g_qkv[0] + (size_t)b * T_ * H_;
    const float* k = g_qkv[1] + (size_t)b * T_ * H_;
    const float* v = g_qkv[2] + (size_t)b * T_ * H_;

    // Load K (transposed) and V (float2 interleaved) into shared.
    for (int f = tid; f < T_ * H_ / 4; f += NW * 32) {
        int j  = f >> 4;
        int h0 = (f & 15) * 4;
        float4 tk = *(const float4*)&k[(size_t)j * H_ + h0];
        s->kT[h0 + 0][j] = tk.x;
        s->kT[h0 + 1][j] = tk.y;
        s->kT[h0 + 2][j] = tk.z;
        s->kT[h0 + 3][j] = tk.w;
        float4 tv = *(const float4*)&v[(size_t)j * H_ + h0];
        s->vs[j][h0 / 2]     = make_float2(tv.x, tv.y);
        s->vs[j][h0 / 2 + 1] = make_float2(tv.z, tv.w);
    }
    __syncthreads();

    const float scale = 0.05103103630798287f;  // 384^-0.5 (NOTE: EMB, not HEAD)

    for (int t = w; t < T_; t += NW) {
        // Stage q row in shared (broadcast-friendly reads below).
        const float* qr = q + (size_t)t * H_;
        s->qrow[w][lane]      = qr[lane];
        s->qrow[w][lane + 32] = qr[lane + 32];
        __syncwarp();

        const int ni = (t >> 5) + 1;   // uniform across warp

        float sc[8];
        #pragma unroll
        for (int i = 0; i < 8; i++) sc[i] = -INFINITY;

        #pragma unroll 1
        for (int i = 0; i < ni; i++) {
            const int j = lane + 32 * i;
            float acc = 0.0f;
            #pragma unroll
            for (int h = 0; h < H_; h++)
                acc += s->qrow[w][h] * s->kT[h][j];
            sc[i] = (j <= t) ? acc * scale : -INFINITY;
        }

        // Row max (per-lane then warp reduce)
        float m = -INFINITY;
        #pragma unroll
        for (int i = 0; i < 8; i++) m = fmaxf(m, sc[i]);
        #pragma unroll
        for (int o = 16; o > 0; o >>= 1)
            m = fmaxf(m, __shfl_xor_sync(0xffffffffu, m, o));

        // exp + sum
        float p[8];
        float sum = 0.0f;
        #pragma unroll
        for (int i = 0; i < 8; i++) {
            p[i] = __expf(sc[i] - m);   // exp(-inf) -> 0 for masked entries
            sum += p[i];
        }
        #pragma unroll
        for (int o = 16; o > 0; o >>= 1)
            sum += __shfl_xor_sync(0xffffffffu, sum, o);
        const float inv = 1.0f / sum;

        // Stage normalized weights for this row.
        #pragma unroll 1
        for (int i = 0; i < ni; i++)
            s->wbuf[w][lane + 32 * i] = p[i] * inv;
        __syncwarp();

        // out[t][2*lane], out[t][2*lane+1] = sum_j w[j] * v[j][h]
        float2 acc = make_float2(0.0f, 0.0f);
        #pragma unroll 4
        for (int j = 0; j <= t; j++) {
            float  ww = s->wbuf[w][j];
            float2 vv = s->vs[j][lane];
            acc.x += ww * vv.x;
            acc.y += ww * vv.y;
        }
        *(float2*)&out[((size_t)b * T_ + t) * H_ + lane * 2] = acc;
        __syncwarp();   // protect wbuf/qrow against next iteration's writes
    }
}

// ---------------------------------------------------------------------------
extern "C" void kernel_launch(void* const* d_in, const int* in_sizes, int n_in,
                              void* d_out, int out_size)
{
    const float* x  = (const float*)d_in[0];
    const float* Wq = (const float*)d_in[1];
    const float* Wk = (const float*)d_in[2];
    const float* Wv = (const float*)d_in[3];
    float* out = (float*)d_out;

    (void)in_sizes; (void)n_in; (void)out_size;

    // QKV projections: grid (1, M/128, 3)
    dim3 g1(1, M_ / 128, 3);
    qkv_gemm<<<g1, 256>>>(x, Wq, Wk, Wv);

    // Attention: one block per batch element, 148 KB dynamic smem.
    cudaFuncSetAttribute(attn_kernel,
                         cudaFuncAttributeMaxDynamicSharedMemorySize,
                         (int)sizeof(AttnSmem));
    attn_kernel<<<B_, 512, sizeof(AttnSmem)>>>(out);
}

// round 3
// speedup vs baseline: 1.3018x; 1.3018x over previous
#include <cuda_runtime.h>
#include <cuda_bf16.h>
#include <cstdint>

#define B_   256
#define T_   256
#define EMB_ 384
#define H_   64
#define M_   (B_*T_)

// Scratch: q,k,v projections [3][B*T][H], and pre-split weights [w][hi/lo][n][k]
__device__ float g_qkv[3][(size_t)M_ * H_];
__device__ __align__(16) __nv_bfloat16 g_wt[3][2][H_][EMB_];

#define SW128(o) ((o) ^ ((((uint32_t)(o)) >> 3) & 0x70))

__device__ __forceinline__ uint32_t smem_u32(const void* p) {
    uint32_t a;
    asm("{ .reg .u64 t; cvta.to.shared.u64 t, %1; cvt.u32.u64 %0, t; }"
        : "=r"(a) : "l"(p));
    return a;
}

__device__ __forceinline__ void ldsm4(uint32_t* r, uint32_t addr) {
    asm volatile("ldmatrix.sync.aligned.m8n8.x4.shared.b16 {%0,%1,%2,%3}, [%4];"
                 : "=r"(r[0]), "=r"(r[1]), "=r"(r[2]), "=r"(r[3]) : "r"(addr));
}

__device__ __forceinline__ void mma16816(float* d, const uint32_t* a,
                                         uint32_t b0, uint32_t b1) {
    asm volatile(
        "mma.sync.aligned.m16n8k16.row.col.f32.bf16.bf16.f32 "
        "{%0,%1,%2,%3}, {%4,%5,%6,%7}, {%8,%9}, {%0,%1,%2,%3};"
        : "+f"(d[0]), "+f"(d[1]), "+f"(d[2]), "+f"(d[3])
        : "r"(a[0]), "r"(a[1]), "r"(a[2]), "r"(a[3]), "r"(b0), "r"(b1));
}

__device__ __forceinline__ uint32_t pack2(__nv_bfloat16 a, __nv_bfloat16 b) {
    return (uint32_t)__bfloat16_as_ushort(a) | ((uint32_t)__bfloat16_as_ushort(b) << 16);
}

// ---------------------------------------------------------------------------
// Kernel 0: pre-split W into bf16 hi/lo, transposed to [n][k]
// ---------------------------------------------------------------------------
__global__ void wconv(const float* __restrict__ Wq, const float* __restrict__ Wk,
                      const float* __restrict__ Wv) {
    int idx = blockIdx.x * 256 + threadIdx.x;
    if (idx >= 3 * EMB_ * H_) return;
    int w = idx / (EMB_ * H_);
    int r = idx % (EMB_ * H_);
    int k = r / H_;
    int n = r % H_;
    const float* W = (w == 0) ? Wq : (w == 1) ? Wk : Wv;
    float v = W[k * H_ + n];
    __nv_bfloat16 hi = __float2bfloat16(v);
    __nv_bfloat16 lo = __float2bfloat16(v - __bfloat162float(hi));
    g_wt[w][0][n][k] = hi;
    g_wt[w][1][n][k] = lo;
}

// ---------------------------------------------------------------------------
// Kernel 1: QKV projection via mma.sync bf16 3-term split.
// 256 threads / 8 warps. CTA = 128 M-rows x (3 weights * 64 N).
// Warp w owns rows [w*16, w*16+16). acc[3][8][4] fp32 per thread.
// smem (dynamic, 160 KB):
//   x tiles:  stage st at st*32768        (hi 16 KB, lo at +16384)
//   W tiles:  65536 + st*49152 + (w2*2+sp)*8192   (64 n-rows x 128 B)
// ---------------------------------------------------------------------------
#define SM_W0    65536
#define SMEM_SZ  (SM_W0 + 2*49152)

__global__ __launch_bounds__(256) void qkv_mm(const float* __restrict__ x)
{
    extern __shared__ char smem[];
    const uint32_t sb = smem_u32(smem);
    const int tid  = threadIdx.x;
    const int wid  = tid >> 5;
    const int lane = tid & 31;
    const int m0   = blockIdx.x * 128;

    float acc[3][8][4] = {};

    // ldmatrix lane-address components (computed once)
    const int a_row  = wid * 16 + (lane & 7) + ((lane >> 3) & 1) * 8;
    const int a_colb = (lane >> 4) * 16;
    const int b_n    = (lane >> 4) * 8 + (lane & 7);
    const int b_colb = ((lane >> 3) & 1) * 16;

    #pragma unroll 1
    for (int c = 0; c < 6; c++) {
        // ---- load chunk c into stage c&1 ----
        {
            const int st = c & 1;
            const int k0 = c * 64;
            char* xh = smem + st * 32768;
            char* xl = xh + 16384;
            #pragma unroll
            for (int it = 0; it < 8; it++) {
                int f   = tid + it * 256;
                int row = f >> 4;
                int kc  = (f & 15) * 4;
                float4 v = *(const float4*)&x[(size_t)(m0 + row) * EMB_ + k0 + kc];
                __nv_bfloat16 h0 = __float2bfloat16(v.x);
                __nv_bfloat16 h1 = __float2bfloat16(v.y);
                __nv_bfloat16 h2 = __float2bfloat16(v.z);
                __nv_bfloat16 h3 = __float2bfloat16(v.w);
                __nv_bfloat16 l0 = __float2bfloat16(v.x - __bfloat162float(h0));
                __nv_bfloat16 l1 = __float2bfloat16(v.y - __bfloat162float(h1));
                __nv_bfloat16 l2 = __float2bfloat16(v.z - __bfloat162float(h2));
                __nv_bfloat16 l3 = __float2bfloat16(v.w - __bfloat162float(h3));
                uint32_t off = SW128(row * 128 + kc * 2);
                uint2 hp, lp;
                hp.x = pack2(h0, h1);  hp.y = pack2(h2, h3);
                lp.x = pack2(l0, l1);  lp.y = pack2(l2, l3);
                *(uint2*)(xh + off) = hp;
                *(uint2*)(xl + off) = lp;
            }
            char* wb = smem + SM_W0 + st * 49152;
            #pragma unroll
            for (int it = 0; it < 12; it++) {
                int f  = tid + it * 256;        // 0..3071
                int w2 = f >> 10;
                int r  = f & 1023;
                int sp = r >> 9;
                int r2 = r & 511;
                int n  = r2 >> 3;
                int q8 = r2 & 7;
                uint4 v = *(const uint4*)&g_wt[w2][sp][n][k0 + q8 * 8];
                *(uint4*)(wb + (w2*2 + sp) * 8192 + SW128(n * 128 + q8 * 16)) = v;
            }
        }
        __syncthreads();

        // ---- compute chunk c from stage c&1 ----
        {
            const int st = c & 1;
            const uint32_t xh = sb + st * 32768;
            const uint32_t xl = xh + 16384;
            const uint32_t wbase = sb + SM_W0 + st * 49152;
            #pragma unroll
            for (int ks = 0; ks < 4; ks++) {
                uint32_t ah[4], al[4];
                const uint32_t aoff = SW128(a_row * 128 + ks * 32 + a_colb);
                ldsm4(ah, xh + aoff);
                ldsm4(al, xl + aoff);
                #pragma unroll
                for (int w2 = 0; w2 < 3; w2++) {
                    const uint32_t wt = wbase + w2 * 16384;
                    #pragma unroll
                    for (int np = 0; np < 4; np++) {   // pair of n-tiles (16 n)
                        const uint32_t boff =
                            SW128((np * 16 + b_n) * 128 + ks * 32 + b_colb);
                        uint32_t bh[4], bl[4];
                        ldsm4(bh, wt + boff);
                        ldsm4(bl, wt + 8192 + boff);
                        mma16816(acc[w2][2*np],   ah, bh[0], bh[1]);  // hi*hi
                        mma16816(acc[w2][2*np],   ah, bl[0], bl[1]);  // hi*lo
                        mma16816(acc[w2][2*np],   al, bh[0], bh[1]);  // lo*hi
                        mma16816(acc[w2][2*np+1], ah, bh[2], bh[3]);
                        mma16816(acc[w2][2*np+1], ah, bl[2], bl[3]);
                        mma16816(acc[w2][2*np+1], al, bh[2], bh[3]);
                    }
                }
            }
        }
        __syncthreads();
    }

    // ---- epilogue: D fragments -> g_qkv ----
    const int g  = lane >> 2;
    const int c2 = (lane & 3) * 2;
    const int r0 = m0 + wid * 16 + g;
    #pragma unroll
    for (int w2 = 0; w2 < 3; w2++) {
        #pragma unroll
        for (int nt = 0; nt < 8; nt++) {
            int n = nt * 8 + c2;
            *(float2*)&g_qkv[w2][(size_t)r0 * H_ + n] =
                make_float2(acc[w2][nt][0], acc[w2][nt][1]);
            *(float2*)&g_qkv[w2][(size_t)(r0 + 8) * H_ + n] =
                make_float2(acc[w2][nt][2], acc[w2][nt][3]);
        }
    }
}

// ---------------------------------------------------------------------------
// Kernel 2: causal attention, one CTA per batch element. 16 warps.
// q held in registers per 16-wide h-block.
// ---------------------------------------------------------------------------
#define NW 16

struct AttnSmem {
    float  kT[H_][T_];        // K transposed                     (64 KB)
    float2 vs[T_][H_ / 2];    // V interleaved as float2          (64 KB)
    float  wbuf[NW][T_];      // per-warp softmax weights         (16 KB)
};

__global__ __launch_bounds__(512) void attn_kernel(float* __restrict__ out)
{
    extern __shared__ char smem_raw[];
    AttnSmem* s = (AttnSmem*)smem_raw;

    const int b    = blockIdx.x;
    const int tid  = threadIdx.x;
    const int lane = tid & 31;
    const int w    = tid >> 5;

    const float* q = g_qkv[0] + (size_t)b * T_ * H_;
    const float* k = g_qkv[1] + (size_t)b * T_ * H_;
    const float* v = g_qkv[2] + (size_t)b * T_ * H_;

    for (int f = tid; f < T_ * H_ / 4; f += NW * 32) {
        int j  = f >> 4;
        int h0 = (f & 15) * 4;
        float4 tk = *(const float4*)&k[(size_t)j * H_ + h0];
        s->kT[h0 + 0][j] = tk.x;
        s->kT[h0 + 1][j] = tk.y;
        s->kT[h0 + 2][j] = tk.z;
        s->kT[h0 + 3][j] = tk.w;
        float4 tv = *(const float4*)&v[(size_t)j * H_ + h0];
        s->vs[j][h0 / 2]     = make_float2(tv.x, tv.y);
        s->vs[j][h0 / 2 + 1] = make_float2(tv.z, tv.w);
    }
    __syncthreads();

    const float scale = 0.05103103630798287f;  // 384^-0.5 (EMB, not HEAD)

    for (int t = w; t < T_; t += NW) {
        const int ni = (t >> 5) + 1;
        const float* qr = q + (size_t)t * H_;

        float sc[8];
        #pragma unroll
        for (int i = 0; i < 8; i++) sc[i] = 0.0f;

        #pragma unroll
        for (int hb = 0; hb < 4; hb++) {
            const float4 q0 = *(const float4*)&qr[hb * 16 + 0];
            const float4 q1 = *(const float4*)&qr[hb * 16 + 4];
            const float4 q2 = *(const float4*)&qr[hb * 16 + 8];
            const float4 q3 = *(const float4*)&qr[hb * 16 + 12];
            #pragma unroll 1
            for (int i = 0; i < ni; i++) {
                const int j = lane + 32 * i;
                float a = 0.0f;
                a += q0.x * s->kT[hb*16 +  0][j];
                a += q0.y * s->kT[hb*16 +  1][j];
                a += q0.z * s->kT[hb*16 +  2][j];
                a += q0.w * s->kT[hb*16 +  3][j];
                a += q1.x * s->kT[hb*16 +  4][j];
                a += q1.y * s->kT[hb*16 +  5][j];
                a += q1.z * s->kT[hb*16 +  6][j];
                a += q1.w * s->kT[hb*16 +  7][j];
                a += q2.x * s->kT[hb*16 +  8][j];
                a += q2.y * s->kT[hb*16 +  9][j];
                a += q2.z * s->kT[hb*16 + 10][j];
                a += q2.w * s->kT[hb*16 + 11][j];
                a += q3.x * s->kT[hb*16 + 12][j];
                a += q3.y * s->kT[hb*16 + 13][j];
                a += q3.z * s->kT[hb*16 + 14][j];
                a += q3.w * s->kT[hb*16 + 15][j];
                sc[i] += a;
            }
        }

        #pragma unroll
        for (int i = 0; i < 8; i++) {
            const int j = lane + 32 * i;
            sc[i] = (j <= t) ? sc[i] * scale : -INFINITY;
        }

        float m = -INFINITY;
        #pragma unroll
        for (int i = 0; i < 8; i++) m = fmaxf(m, sc[i]);
        #pragma unroll
        for (int o = 16; o > 0; o >>= 1)
            m = fmaxf(m, __shfl_xor_sync(0xffffffffu, m, o));

        float p[8];
        float sum = 0.0f;
        #pragma unroll
        for (int i = 0; i < 8; i++) {
            p[i] = __expf(sc[i] - m);
            sum += p[i];
        }
        #pragma unroll
        for (int o = 16; o > 0; o >>= 1)
            sum += __shfl_xor_sync(0xffffffffu, sum, o);
        const float inv = 1.0f / sum;

        #pragma unroll 1
        for (int i = 0; i < ni; i++)
            s->wbuf[w][lane + 32 * i] = p[i] * inv;
        __syncwarp();

        float2 acc = make_float2(0.0f, 0.0f);
        #pragma unroll 4
        for (int j = 0; j <= t; j++) {
            float  ww = s->wbuf[w][j];
            float2 vv = s->vs[j][lane];
            acc.x += ww * vv.x;
            acc.y += ww * vv.y;
        }
        *(float2*)&out[((size_t)b * T_ + t) * H_ + lane * 2] = acc;
        __syncwarp();
    }
}

// ---------------------------------------------------------------------------
extern "C" void kernel_launch(void* const* d_in, const int* in_sizes, int n_in,
                              void* d_out, int out_size)
{
    const float* x  = (const float*)d_in[0];
    const float* Wq = (const float*)d_in[1];
    const float* Wk = (const float*)d_in[2];
    const float* Wv = (const float*)d_in[3];
    float* out = (float*)d_out;
    (void)in_sizes; (void)n_in; (void)out_size;

    wconv<<<(3 * EMB_ * H_ + 255) / 256, 256>>>(Wq, Wk, Wv);

    cudaFuncSetAttribute(qkv_mm, cudaFuncAttributeMaxDynamicSharedMemorySize, SMEM_SZ);
    qkv_mm<<<M_ / 128, 256, SMEM_SZ>>>(x);

    cudaFuncSetAttribute(attn_kernel, cudaFuncAttributeMaxDynamicSharedMemorySize,
                         (int)sizeof(AttnSmem));
    attn_kernel<<<B_, 512, sizeof(AttnSmem)>>>(out);
}

// round 4
// speedup vs baseline: 3.0051x; 2.3083x over previous
#include <cuda_runtime.h>
#include <cuda_bf16.h>
#include <cstdint>

#define B_   256
#define T_   256
#define EMB_ 384
#define H_   64
#define M_   (B_*T_)

// Scratch: q,k,v projections [3][B*T][H], and pre-split weights [w][hi/lo][n][k]
__device__ float g_qkv[3][(size_t)M_ * H_];
__device__ __align__(16) __nv_bfloat16 g_wt[3][2][H_][EMB_];

#define SW128(o) ((o) ^ ((((uint32_t)(o)) >> 3) & 0x70))

__device__ __forceinline__ uint32_t smem_u32(const void* p) {
    uint32_t a;
    asm("{ .reg .u64 t; cvta.to.shared.u64 t, %1; cvt.u32.u64 %0, t; }"
        : "=r"(a) : "l"(p));
    return a;
}

__device__ __forceinline__ void ldsm4(uint32_t* r, uint32_t addr) {
    asm volatile("ldmatrix.sync.aligned.m8n8.x4.shared.b16 {%0,%1,%2,%3}, [%4];"
                 : "=r"(r[0]), "=r"(r[1]), "=r"(r[2]), "=r"(r[3]) : "r"(addr));
}

__device__ __forceinline__ void ldsm4t(uint32_t* r, uint32_t addr) {
    asm volatile("ldmatrix.sync.aligned.m8n8.x4.trans.shared.b16 {%0,%1,%2,%3}, [%4];"
                 : "=r"(r[0]), "=r"(r[1]), "=r"(r[2]), "=r"(r[3]) : "r"(addr));
}

__device__ __forceinline__ void mma16816(float* d, const uint32_t* a,
                                         uint32_t b0, uint32_t b1) {
    asm volatile(
        "mma.sync.aligned.m16n8k16.row.col.f32.bf16.bf16.f32 "
        "{%0,%1,%2,%3}, {%4,%5,%6,%7}, {%8,%9}, {%0,%1,%2,%3};"
        : "+f"(d[0]), "+f"(d[1]), "+f"(d[2]), "+f"(d[3])
        : "r"(a[0]), "r"(a[1]), "r"(a[2]), "r"(a[3]), "r"(b0), "r"(b1));
}

__device__ __forceinline__ uint32_t pack2(__nv_bfloat16 a, __nv_bfloat16 b) {
    return (uint32_t)__bfloat16_as_ushort(a) | ((uint32_t)__bfloat16_as_ushort(b) << 16);
}

__device__ __forceinline__ uint32_t hi2(float a, float b) {
    return pack2(__float2bfloat16(a), __float2bfloat16(b));
}
__device__ __forceinline__ uint32_t lo2(float a, float b) {
    __nv_bfloat16 ha = __float2bfloat16(a), hb = __float2bfloat16(b);
    return pack2(__float2bfloat16(a - __bfloat162float(ha)),
                 __float2bfloat16(b - __bfloat162float(hb)));
}

// ---------------------------------------------------------------------------
// Kernel 0: pre-split W into bf16 hi/lo, transposed to [n][k]
// ---------------------------------------------------------------------------
__global__ void wconv(const float* __restrict__ Wq, const float* __restrict__ Wk,
                      const float* __restrict__ Wv) {
    int idx = blockIdx.x * 256 + threadIdx.x;
    if (idx >= 3 * EMB_ * H_) return;
    int w = idx / (EMB_ * H_);
    int r = idx % (EMB_ * H_);
    int k = r / H_;
    int n = r % H_;
    const float* W = (w == 0) ? Wq : (w == 1) ? Wk : Wv;
    float v = W[k * H_ + n];
    __nv_bfloat16 hi = __float2bfloat16(v);
    __nv_bfloat16 lo = __float2bfloat16(v - __bfloat162float(hi));
    g_wt[w][0][n][k] = hi;
    g_wt[w][1][n][k] = lo;
}

// ---------------------------------------------------------------------------
// Kernel 1: QKV projection via mma.sync bf16 3-term split (unchanged, R3).
// ---------------------------------------------------------------------------
#define SM_W0    65536
#define SMEM_SZ  (SM_W0 + 2*49152)

__global__ __launch_bounds__(256) void qkv_mm(const float* __restrict__ x)
{
    extern __shared__ char smem[];
    const uint32_t sb = smem_u32(smem);
    const int tid  = threadIdx.x;
    const int wid  = tid >> 5;
    const int lane = tid & 31;
    const int m0   = blockIdx.x * 128;

    float acc[3][8][4] = {};

    const int a_row  = wid * 16 + (lane & 7) + ((lane >> 3) & 1) * 8;
    const int a_colb = (lane >> 4) * 16;
    const int b_n    = (lane >> 4) * 8 + (lane & 7);
    const int b_colb = ((lane >> 3) & 1) * 16;

    #pragma unroll 1
    for (int c = 0; c < 6; c++) {
        {
            const int st = c & 1;
            const int k0 = c * 64;
            char* xh = smem + st * 32768;
            char* xl = xh + 16384;
            #pragma unroll
            for (int it = 0; it < 8; it++) {
                int f   = tid + it * 256;
                int row = f >> 4;
                int kc  = (f & 15) * 4;
                float4 v = *(const float4*)&x[(size_t)(m0 + row) * EMB_ + k0 + kc];
                uint32_t off = SW128(row * 128 + kc * 2);
                uint2 hp, lp;
                hp.x = hi2(v.x, v.y);  hp.y = hi2(v.z, v.w);
                lp.x = lo2(v.x, v.y);  lp.y = lo2(v.z, v.w);
                *(uint2*)(xh + off) = hp;
                *(uint2*)(xl + off) = lp;
            }
            char* wb = smem + SM_W0 + st * 49152;
            #pragma unroll
            for (int it = 0; it < 12; it++) {
                int f  = tid + it * 256;
                int w2 = f >> 10;
                int r  = f & 1023;
                int sp = r >> 9;
                int r2 = r & 511;
                int n  = r2 >> 3;
                int q8 = r2 & 7;
                uint4 v = *(const uint4*)&g_wt[w2][sp][n][k0 + q8 * 8];
                *(uint4*)(wb + (w2*2 + sp) * 8192 + SW128(n * 128 + q8 * 16)) = v;
            }
        }
        __syncthreads();
        {
            const int st = c & 1;
            const uint32_t xh = sb + st * 32768;
            const uint32_t xl = xh + 16384;
            const uint32_t wbase = sb + SM_W0 + st * 49152;
            #pragma unroll
            for (int ks = 0; ks < 4; ks++) {
                uint32_t ah[4], al[4];
                const uint32_t aoff = SW128(a_row * 128 + ks * 32 + a_colb);
                ldsm4(ah, xh + aoff);
                ldsm4(al, xl + aoff);
                #pragma unroll
                for (int w2 = 0; w2 < 3; w2++) {
                    const uint32_t wt = wbase + w2 * 16384;
                    #pragma unroll
                    for (int np = 0; np < 4; np++) {
                        const uint32_t boff =
                            SW128((np * 16 + b_n) * 128 + ks * 32 + b_colb);
                        uint32_t bh[4], bl[4];
                        ldsm4(bh, wt + boff);
                        ldsm4(bl, wt + 8192 + boff);
                        mma16816(acc[w2][2*np],   ah, bh[0], bh[1]);
                        mma16816(acc[w2][2*np],   ah, bl[0], bl[1]);
                        mma16816(acc[w2][2*np],   al, bh[0], bh[1]);
                        mma16816(acc[w2][2*np+1], ah, bh[2], bh[3]);
                        mma16816(acc[w2][2*np+1], ah, bl[2], bl[3]);
                        mma16816(acc[w2][2*np+1], al, bh[2], bh[3]);
                    }
                }
            }
        }
        __syncthreads();
    }

    const int g  = lane >> 2;
    const int c2 = (lane & 3) * 2;
    const int r0 = m0 + wid * 16 + g;
    #pragma unroll
    for (int w2 = 0; w2 < 3; w2++) {
        #pragma unroll
        for (int nt = 0; nt < 8; nt++) {
            int n = nt * 8 + c2;
            *(float2*)&g_qkv[w2][(size_t)r0 * H_ + n] =
                make_float2(acc[w2][nt][0], acc[w2][nt][1]);
            *(float2*)&g_qkv[w2][(size_t)(r0 + 8) * H_ + n] =
                make_float2(acc[w2][nt][2], acc[w2][nt][3]);
        }
    }
}

// ---------------------------------------------------------------------------
// Kernel 2: tensor-core causal attention. CTA = 1 batch, 8 warps, 256 thr.
// K/V in smem as bf16 hi/lo (SW128). Warp owns m-tiles wid and 15-wid.
// No max-subtraction (scores bounded |s| < ~5 << 88): exp -> rowsum -> PV,
// final scale by 1/rowsum.
// smem: Khi 0, Klo 32K, Vhi 64K, Vlo 96K  (128 KB)
// ---------------------------------------------------------------------------
#define ATTN_SMEM 131072

__global__ __launch_bounds__(256) void attn_tc(float* __restrict__ out)
{
    extern __shared__ char smem[];
    const uint32_t sb = smem_u32(smem);
    const int b    = blockIdx.x;
    const int tid  = threadIdx.x;
    const int wid  = tid >> 5;
    const int lane = tid & 31;

    const float* qq = g_qkv[0] + (size_t)b * T_ * H_;
    const float* kk = g_qkv[1] + (size_t)b * T_ * H_;
    const float* vv = g_qkv[2] + (size_t)b * T_ * H_;

    // Fill K/V hi/lo tiles (row j = 64 bf16 = 128 B, SW128)
    char* khp = smem;
    char* klp = smem + 32768;
    char* vhp = smem + 65536;
    char* vlp = smem + 98304;
    #pragma unroll
    for (int it = 0; it < 16; it++) {
        int f  = tid + it * 256;
        int j  = f >> 4;
        int h0 = (f & 15) * 4;
        uint32_t off = SW128(j * 128 + h0 * 2);
        float4 a = *(const float4*)&kk[(size_t)j * H_ + h0];
        uint2 hp, lp;
        hp.x = hi2(a.x, a.y);  hp.y = hi2(a.z, a.w);
        lp.x = lo2(a.x, a.y);  lp.y = lo2(a.z, a.w);
        *(uint2*)(khp + off) = hp;
        *(uint2*)(klp + off) = lp;
        float4 c = *(const float4*)&vv[(size_t)j * H_ + h0];
        hp.x = hi2(c.x, c.y);  hp.y = hi2(c.z, c.w);
        lp.x = lo2(c.x, c.y);  lp.y = lo2(c.z, c.w);
        *(uint2*)(vhp + off) = hp;
        *(uint2*)(vlp + off) = lp;
    }
    __syncthreads();

    const float scale = 0.05103103630798287f;  // 384^-0.5 (EMB, not HEAD)
    const int g  = lane >> 2;
    const int c4 = lane & 3;
    // ldmatrix lane-address pieces (rows within a 16-row group)
    const int lrow  = (lane & 7) + ((lane >> 3) & 1) * 8;
    const int lcolh = ((lane >> 4) & 1) * 16;

    const uint32_t kh = sb;
    const uint32_t kl = sb + 32768;
    const uint32_t vh = sb + 65536;
    const uint32_t vl = sb + 98304;

    #pragma unroll 1
    for (int half = 0; half < 2; half++) {
        const int tt = (half == 0) ? wid : 15 - wid;
        const int r0 = tt * 16;

        // Q fragments (hi/lo), scaled: a-regs rr: row g+(rr&1)*8, col (rr>>1)*8+2c
        uint32_t qfh[4][4], qfl[4][4];
        #pragma unroll
        for (int kc = 0; kc < 4; kc++) {
            #pragma unroll
            for (int rr = 0; rr < 4; rr++) {
                int row = r0 + g + (rr & 1) * 8;
                int col = kc * 16 + (rr >> 1) * 8 + 2 * c4;
                float2 v = *(const float2*)&qq[(size_t)row * H_ + col];
                v.x *= scale;  v.y *= scale;
                qfh[kc][rr] = hi2(v.x, v.y);
                qfl[kc][rr] = lo2(v.x, v.y);
            }
        }

        float oacc[8][4] = {};
        float sum0 = 0.0f, sum1 = 0.0f;
        const int nb = (r0 + 47) >> 5;

        #pragma unroll 1
        for (int blk = 0; blk < nb; blk++) {
            const int s0 = blk * 32;
            float sacc[4][4] = {};

            // ---- S = Q K^T over this 32-col block ----
            #pragma unroll
            for (int kc = 0; kc < 4; kc++) {
                uint32_t bh[8], bl[8];
                #pragma unroll
                for (int grp = 0; grp < 2; grp++) {
                    uint32_t off = SW128((s0 + grp * 16 + lrow) * 128 + kc * 32 + lcolh);
                    ldsm4(&bh[grp * 4], kh + off);
                    ldsm4(&bl[grp * 4], kl + off);
                }
                #pragma unroll
                for (int nt = 0; nt < 4; nt++) {
                    const int base = (nt >> 1) * 4;
                    const uint32_t b0h = bh[base + (nt & 1)];
                    const uint32_t b1h = bh[base + (nt & 1) + 2];
                    const uint32_t b0l = bl[base + (nt & 1)];
                    const uint32_t b1l = bl[base + (nt & 1) + 2];
                    mma16816(sacc[nt], qfh[kc], b0h, b1h);
                    mma16816(sacc[nt], qfh[kc], b0l, b1l);
                    mma16816(sacc[nt], qfl[kc], b0h, b1h);
                }
            }

            // ---- exp + causal mask + rowsum ----
            const bool last = (blk == nb - 1);
            float p[4][4];
            #pragma unroll
            for (int nt = 0; nt < 4; nt++) {
                #pragma unroll
                for (int rr = 0; rr < 4; rr++) {
                    int j = s0 + nt * 8 + 2 * c4 + (rr & 1);
                    int t = r0 + g + (rr >> 1) * 8;
                    float e = (!last || j <= t) ? __expf(sacc[nt][rr]) : 0.0f;
                    p[nt][rr] = e;
                    if (rr < 2) sum0 += e; else sum1 += e;
                }
            }

            // ---- P fragments (hi/lo) as A operands: kchunk kc2 <- ntiles 2kc2,2kc2+1
            uint32_t pfh[2][4], pfl[2][4];
            #pragma unroll
            for (int kc2 = 0; kc2 < 2; kc2++) {
                const float* p0 = p[2 * kc2];
                const float* p1 = p[2 * kc2 + 1];
                pfh[kc2][0] = hi2(p0[0], p0[1]);
                pfh[kc2][1] = hi2(p0[2], p0[3]);
                pfh[kc2][2] = hi2(p1[0], p1[1]);
                pfh[kc2][3] = hi2(p1[2], p1[3]);
                pfl[kc2][0] = lo2(p0[0], p0[1]);
                pfl[kc2][1] = lo2(p0[2], p0[3]);
                pfl[kc2][2] = lo2(p1[0], p1[1]);
                pfl[kc2][3] = lo2(p1[2], p1[3]);
            }

            // ---- O += P V ----
            #pragma unroll
            for (int kc2 = 0; kc2 < 2; kc2++) {
                #pragma unroll
                for (int np = 0; np < 4; np++) {
                    uint32_t off = SW128((s0 + kc2 * 16 + lrow) * 128 + np * 32 + lcolh);
                    uint32_t vbh[4], vbl[4];
                    ldsm4t(vbh, vh + off);
                    ldsm4t(vbl, vl + off);
                    mma16816(oacc[2*np],   pfh[kc2], vbh[0], vbh[1]);
                    mma16816(oacc[2*np],   pfh[kc2], vbl[0], vbl[1]);
                    mma16816(oacc[2*np],   pfl[kc2], vbh[0], vbh[1]);
                    mma16816(oacc[2*np+1], pfh[kc2], vbh[2], vbh[3]);
                    mma16816(oacc[2*np+1], pfh[kc2], vbl[2], vbl[3]);
                    mma16816(oacc[2*np+1], pfl[kc2], vbh[2], vbh[3]);
                }
            }
        }

        // ---- rowsum reduce across quad lanes, scale, store ----
        sum0 += __shfl_xor_sync(0xffffffffu, sum0, 1);
        sum0 += __shfl_xor_sync(0xffffffffu, sum0, 2);
        sum1 += __shfl_xor_sync(0xffffffffu, sum1, 1);
        sum1 += __shfl_xor_sync(0xffffffffu, sum1, 2);
        const float inv0 = 1.0f / sum0;
        const float inv1 = 1.0f / sum1;

        float* orow0 = out + ((size_t)b * T_ + r0 + g) * H_;
        float* orow1 = out + ((size_t)b * T_ + r0 + g + 8) * H_;
        #pragma unroll
        for (int nt = 0; nt < 8; nt++) {
            int n = nt * 8 + 2 * c4;
            *(float2*)&orow0[n] = make_float2(oacc[nt][0] * inv0, oacc[nt][1] * inv0);
            *(float2*)&orow1[n] = make_float2(oacc[nt][2] * inv1, oacc[nt][3] * inv1);
        }
    }
}

// ---------------------------------------------------------------------------
extern "C" void kernel_launch(void* const* d_in, const int* in_sizes, int n_in,
                              void* d_out, int out_size)
{
    const float* x  = (const float*)d_in[0];
    const float* Wq = (const float*)d_in[1];
    const float* Wk = (const float*)d_in[2];
    const float* Wv = (const float*)d_in[3];
    float* out = (float*)d_out;
    (void)in_sizes; (void)n_in; (void)out_size;

    wconv<<<(3 * EMB_ * H_ + 255) / 256, 256>>>(Wq, Wk, Wv);

    cudaFuncSetAttribute(qkv_mm, cudaFuncAttributeMaxDynamicSharedMemorySize, SMEM_SZ);
    qkv_mm<<<M_ / 128, 256, SMEM_SZ>>>(x);

    cudaFuncSetAttribute(attn_tc, cudaFuncAttributeMaxDynamicSharedMemorySize, ATTN_SMEM);
    attn_tc<<<B_, 256, ATTN_SMEM>>>(out);
}

// round 5
// speedup vs baseline: 3.6631x; 1.2190x over previous
#include <cuda_runtime.h>
#include <cuda_bf16.h>
#include <cstdint>

#define B_   256
#define T_   256
#define EMB_ 384
#define H_   64
#define M_   (B_*T_)

// Scratch: q,k,v projections [3][B*T][H], and pre-split weights [w][hi/lo][n][k]
__device__ float g_qkv[3][(size_t)M_ * H_];
__device__ __align__(16) __nv_bfloat16 g_wt[3][2][H_][EMB_];

#define SW128(o) ((o) ^ ((((uint32_t)(o)) >> 3) & 0x70))

__device__ __forceinline__ uint32_t smem_u32(const void* p) {
    uint32_t a;
    asm("{ .reg .u64 t; cvta.to.shared.u64 t, %1; cvt.u32.u64 %0, t; }"
        : "=r"(a) : "l"(p));
    return a;
}

__device__ __forceinline__ void ldsm4(uint32_t* r, uint32_t addr) {
    asm volatile("ldmatrix.sync.aligned.m8n8.x4.shared.b16 {%0,%1,%2,%3}, [%4];"
                 : "=r"(r[0]), "=r"(r[1]), "=r"(r[2]), "=r"(r[3]) : "r"(addr));
}

__device__ __forceinline__ void ldsm4t(uint32_t* r, uint32_t addr) {
    asm volatile("ldmatrix.sync.aligned.m8n8.x4.trans.shared.b16 {%0,%1,%2,%3}, [%4];"
                 : "=r"(r[0]), "=r"(r[1]), "=r"(r[2]), "=r"(r[3]) : "r"(addr));
}

__device__ __forceinline__ void mma16816(float* d, const uint32_t* a,
                                         uint32_t b0, uint32_t b1) {
    asm volatile(
        "mma.sync.aligned.m16n8k16.row.col.f32.bf16.bf16.f32 "
        "{%0,%1,%2,%3}, {%4,%5,%6,%7}, {%8,%9}, {%0,%1,%2,%3};"
        : "+f"(d[0]), "+f"(d[1]), "+f"(d[2]), "+f"(d[3])
        : "r"(a[0]), "r"(a[1]), "r"(a[2]), "r"(a[3]), "r"(b0), "r"(b1));
}

// Fast bf16 hi/lo split: hp = pack(bf16(a), bf16(b)) [low half = a],
// lp = pack of bf16 residuals. 6 ops per 2 floats.
__device__ __forceinline__ void split2(float a, float b, uint32_t& hp, uint32_t& lp) {
    asm("cvt.rn.bf16x2.f32 %0, %1, %2;" : "=r"(hp) : "f"(b), "f"(a));
    float ha = __uint_as_float(hp << 16);
    float hb = __uint_as_float(hp & 0xffff0000u);
    float la = a - ha;
    float lb = b - hb;
    asm("cvt.rn.bf16x2.f32 %0, %1, %2;" : "=r"(lp) : "f"(lb), "f"(la));
}

__device__ __forceinline__ void cp_async16(uint32_t saddr, const void* g) {
    asm volatile("cp.async.cg.shared.global [%0], [%1], 16;" :: "r"(saddr), "l"(g));
}
#define CP_COMMIT() asm volatile("cp.async.commit_group;" ::: "memory")
#define CP_WAIT0()  asm volatile("cp.async.wait_group 0;" ::: "memory")

// ---------------------------------------------------------------------------
// Kernel 0: pre-split W into bf16 hi/lo, transposed to [n][k]
// ---------------------------------------------------------------------------
__global__ void wconv(const float* __restrict__ Wq, const float* __restrict__ Wk,
                      const float* __restrict__ Wv) {
    int idx = blockIdx.x * 256 + threadIdx.x;
    if (idx >= 3 * EMB_ * H_) return;
    int w = idx / (EMB_ * H_);
    int r = idx % (EMB_ * H_);
    int k = r / H_;
    int n = r % H_;
    const float* W = (w == 0) ? Wq : (w == 1) ? Wk : Wv;
    float v = W[k * H_ + n];
    __nv_bfloat16 hi = __float2bfloat16(v);
    __nv_bfloat16 lo = __float2bfloat16(v - __bfloat162float(hi));
    g_wt[w][0][n][k] = hi;
    g_wt[w][1][n][k] = lo;
}

// ---------------------------------------------------------------------------
// Kernel 1: QKV projection, mma.sync bf16 3-term split, software pipelined.
// x chunk c+1 prefetched to regs during compute(c); W via cp.async.
// smem: x stages 2 x (hi 16K + lo 16K) at 0; W stages 2 x 48K at 65536.
// ---------------------------------------------------------------------------
#define SM_W0    65536
#define SMEM_SZ  (SM_W0 + 2*49152)

__device__ __forceinline__ void ldg_x(float4* xr, const float* __restrict__ xb,
                                      int k0, int tid) {
    #pragma unroll
    for (int it = 0; it < 8; it++) {
        int f = tid + it * 256;
        xr[it] = *(const float4*)&xb[(size_t)(f >> 4) * EMB_ + k0 + (f & 15) * 4];
    }
}

__device__ __forceinline__ void sts_x(const float4* xr, char* xh, char* xl, int tid) {
    #pragma unroll
    for (int it = 0; it < 8; it++) {
        int f = tid + it * 256;
        uint32_t off = SW128((f >> 4) * 128 + (f & 15) * 8);
        uint2 hp, lp;
        split2(xr[it].x, xr[it].y, hp.x, lp.x);
        split2(xr[it].z, xr[it].w, hp.y, lp.y);
        *(uint2*)(xh + off) = hp;
        *(uint2*)(xl + off) = lp;
    }
}

__device__ __forceinline__ void cp_w(uint32_t wdst, int k0, int tid) {
    #pragma unroll
    for (int it = 0; it < 12; it++) {
        int f  = tid + it * 256;
        int w2 = f >> 10;
        int r  = f & 1023;
        int sp = r >> 9;
        int r2 = r & 511;
        int n  = r2 >> 3;
        int q8 = r2 & 7;
        cp_async16(wdst + (w2*2 + sp) * 8192 + SW128(n * 128 + q8 * 16),
                   &g_wt[w2][sp][n][k0 + q8 * 8]);
    }
}

__global__ __launch_bounds__(256) void qkv_mm(const float* __restrict__ x)
{
    extern __shared__ char smem[];
    const uint32_t sb = smem_u32(smem);
    const int tid  = threadIdx.x;
    const int wid  = tid >> 5;
    const int lane = tid & 31;
    const int m0   = blockIdx.x * 128;
    const float* xb = x + (size_t)m0 * EMB_;

    float acc[3][8][4] = {};

    const int a_row  = wid * 16 + (lane & 7) + ((lane >> 3) & 1) * 8;
    const int a_colb = (lane >> 4) * 16;
    const int b_n    = (lane >> 4) * 8 + (lane & 7);
    const int b_colb = ((lane >> 3) & 1) * 16;

    float4 xr[8];
    ldg_x(xr, xb, 0, tid);
    cp_w(sb + SM_W0, 0, tid);
    CP_COMMIT();

    #pragma unroll 1
    for (int c = 0; c < 6; c++) {
        const int st = c & 1;
        sts_x(xr, smem + st * 32768, smem + st * 32768 + 16384, tid);
        CP_WAIT0();
        __syncthreads();

        if (c < 5) {
            ldg_x(xr, xb, (c + 1) * 64, tid);
            cp_w(sb + SM_W0 + (st ^ 1) * 49152, (c + 1) * 64, tid);
            CP_COMMIT();
        }

        // compute chunk c from stage st
        const uint32_t xh = sb + st * 32768;
        const uint32_t xl = xh + 16384;
        const uint32_t wbase = sb + SM_W0 + st * 49152;
        #pragma unroll
        for (int ks = 0; ks < 4; ks++) {
            uint32_t ah[4], al[4];
            const uint32_t aoff = SW128(a_row * 128 + ks * 32 + a_colb);
            ldsm4(ah, xh + aoff);
            ldsm4(al, xl + aoff);
            #pragma unroll
            for (int w2 = 0; w2 < 3; w2++) {
                const uint32_t wt = wbase + w2 * 16384;
                #pragma unroll
                for (int np = 0; np < 4; np++) {
                    const uint32_t boff =
                        SW128((np * 16 + b_n) * 128 + ks * 32 + b_colb);
                    uint32_t bh[4], bl[4];
                    ldsm4(bh, wt + boff);
                    ldsm4(bl, wt + 8192 + boff);
                    mma16816(acc[w2][2*np],   ah, bh[0], bh[1]);
                    mma16816(acc[w2][2*np],   ah, bl[0], bl[1]);
                    mma16816(acc[w2][2*np],   al, bh[0], bh[1]);
                    mma16816(acc[w2][2*np+1], ah, bh[2], bh[3]);
                    mma16816(acc[w2][2*np+1], ah, bl[2], bl[3]);
                    mma16816(acc[w2][2*np+1], al, bh[2], bh[3]);
                }
            }
        }
    }

    const int g  = lane >> 2;
    const int c2 = (lane & 3) * 2;
    const int r0 = m0 + wid * 16 + g;
    #pragma unroll
    for (int w2 = 0; w2 < 3; w2++) {
        #pragma unroll
        for (int nt = 0; nt < 8; nt++) {
            int n = nt * 8 + c2;
            *(float2*)&g_qkv[w2][(size_t)r0 * H_ + n] =
                make_float2(acc[w2][nt][0], acc[w2][nt][1]);
            *(float2*)&g_qkv[w2][(size_t)(r0 + 8) * H_ + n] =
                make_float2(acc[w2][nt][2], acc[w2][nt][3]);
        }
    }
}

// ---------------------------------------------------------------------------
// Kernel 2: tensor-core causal attention. CTA = 1 batch, 8 warps.
// K/V bf16 hi/lo in smem; no max-subtraction; exp2 with log2e folded into Q.
// smem: Khi 0, Klo 32K, Vhi 64K, Vlo 96K  (128 KB)
// ---------------------------------------------------------------------------
#define ATTN_SMEM 131072

__global__ __launch_bounds__(256) void attn_tc(float* __restrict__ out)
{
    extern __shared__ char smem[];
    const uint32_t sb = smem_u32(smem);
    const int b    = blockIdx.x;
    const int tid  = threadIdx.x;
    const int wid  = tid >> 5;
    const int lane = tid & 31;

    const float* qq = g_qkv[0] + (size_t)b * T_ * H_;
    const float* kk = g_qkv[1] + (size_t)b * T_ * H_;
    const float* vv = g_qkv[2] + (size_t)b * T_ * H_;

    char* khp = smem;
    char* klp = smem + 32768;
    char* vhp = smem + 65536;
    char* vlp = smem + 98304;
    #pragma unroll
    for (int it = 0; it < 16; it++) {
        int f  = tid + it * 256;
        int j  = f >> 4;
        int h0 = (f & 15) * 4;
        uint32_t off = SW128(j * 128 + h0 * 2);
        float4 a = *(const float4*)&kk[(size_t)j * H_ + h0];
        uint2 hp, lp;
        split2(a.x, a.y, hp.x, lp.x);
        split2(a.z, a.w, hp.y, lp.y);
        *(uint2*)(khp + off) = hp;
        *(uint2*)(klp + off) = lp;
        float4 c = *(const float4*)&vv[(size_t)j * H_ + h0];
        split2(c.x, c.y, hp.x, lp.x);
        split2(c.z, c.w, hp.y, lp.y);
        *(uint2*)(vhp + off) = hp;
        *(uint2*)(vlp + off) = lp;
    }
    __syncthreads();

    // 384^-0.5 * log2(e): exp(s*384^-0.5) == exp2(s * this)
    const float scale_l2e = 0.05103103630798287f * 1.4426950408889634f;
    const int g  = lane >> 2;
    const int c4 = lane & 3;
    const int lrow  = (lane & 7) + ((lane >> 3) & 1) * 8;
    const int lcolh = ((lane >> 4) & 1) * 16;

    const uint32_t kh = sb;
    const uint32_t kl = sb + 32768;
    const uint32_t vh = sb + 65536;
    const uint32_t vl = sb + 98304;

    #pragma unroll 1
    for (int half = 0; half < 2; half++) {
        const int tt = (half == 0) ? wid : 15 - wid;
        const int r0 = tt * 16;

        uint32_t qfh[4][4], qfl[4][4];
        #pragma unroll
        for (int kc = 0; kc < 4; kc++) {
            #pragma unroll
            for (int rr = 0; rr < 4; rr++) {
                int row = r0 + g + (rr & 1) * 8;
                int col = kc * 16 + (rr >> 1) * 8 + 2 * c4;
                float2 v = *(const float2*)&qq[(size_t)row * H_ + col];
                v.x *= scale_l2e;  v.y *= scale_l2e;
                split2(v.x, v.y, qfh[kc][rr], qfl[kc][rr]);
            }
        }

        float oacc[8][4] = {};
        float sum0 = 0.0f, sum1 = 0.0f;
        const int nb = (r0 + 47) >> 5;

        #pragma unroll 1
        for (int blk = 0; blk < nb; blk++) {
            const int s0 = blk * 32;
            float sacc[4][4] = {};

            #pragma unroll
            for (int kc = 0; kc < 4; kc++) {
                uint32_t bh[8], bl[8];
                #pragma unroll
                for (int grp = 0; grp < 2; grp++) {
                    uint32_t off = SW128((s0 + grp * 16 + lrow) * 128 + kc * 32 + lcolh);
                    ldsm4(&bh[grp * 4], kh + off);
                    ldsm4(&bl[grp * 4], kl + off);
                }
                #pragma unroll
                for (int nt = 0; nt < 4; nt++) {
                    const int base = (nt >> 1) * 4;
                    const uint32_t b0h = bh[base + (nt & 1)];
                    const uint32_t b1h = bh[base + (nt & 1) + 2];
                    const uint32_t b0l = bl[base + (nt & 1)];
                    const uint32_t b1l = bl[base + (nt & 1) + 2];
                    mma16816(sacc[nt], qfh[kc], b0h, b1h);
                    mma16816(sacc[nt], qfh[kc], b0l, b1l);
                    mma16816(sacc[nt], qfl[kc], b0h, b1h);
                }
            }

            const bool last = (blk == nb - 1);
            float p[4][4];
            #pragma unroll
            for (int nt = 0; nt < 4; nt++) {
                #pragma unroll
                for (int rr = 0; rr < 4; rr++) {
                    int j = s0 + nt * 8 + 2 * c4 + (rr & 1);
                    int t = r0 + g + (rr >> 1) * 8;
                    float e = (!last || j <= t) ? exp2f(sacc[nt][rr]) : 0.0f;
                    p[nt][rr] = e;
                    if (rr < 2) sum0 += e; else sum1 += e;
                }
            }

            uint32_t pfh[2][4], pfl[2][4];
            #pragma unroll
            for (int kc2 = 0; kc2 < 2; kc2++) {
                const float* p0 = p[2 * kc2];
                const float* p1 = p[2 * kc2 + 1];
                split2(p0[0], p0[1], pfh[kc2][0], pfl[kc2][0]);
                split2(p0[2], p0[3], pfh[kc2][1], pfl[kc2][1]);
                split2(p1[0], p1[1], pfh[kc2][2], pfl[kc2][2]);
                split2(p1[2], p1[3], pfh[kc2][3], pfl[kc2][3]);
            }

            #pragma unroll
            for (int kc2 = 0; kc2 < 2; kc2++) {
                #pragma unroll
                for (int np = 0; np < 4; np++) {
                    uint32_t off = SW128((s0 + kc2 * 16 + lrow) * 128 + np * 32 + lcolh);
                    uint32_t vbh[4], vbl[4];
                    ldsm4t(vbh, vh + off);
                    ldsm4t(vbl, vl + off);
                    mma16816(oacc[2*np],   pfh[kc2], vbh[0], vbh[1]);
                    mma16816(oacc[2*np],   pfh[kc2], vbl[0], vbl[1]);
                    mma16816(oacc[2*np],   pfl[kc2], vbh[0], vbh[1]);
                    mma16816(oacc[2*np+1], pfh[kc2], vbh[2], vbh[3]);
                    mma16816(oacc[2*np+1], pfh[kc2], vbl[2], vbl[3]);
                    mma16816(oacc[2*np+1], pfl[kc2], vbh[2], vbh[3]);
                }
            }
        }

        sum0 += __shfl_xor_sync(0xffffffffu, sum0, 1);
        sum0 += __shfl_xor_sync(0xffffffffu, sum0, 2);
        sum1 += __shfl_xor_sync(0xffffffffu, sum1, 1);
        sum1 += __shfl_xor_sync(0xffffffffu, sum1, 2);
        const float inv0 = 1.0f / sum0;
        const float inv1 = 1.0f / sum1;

        float* orow0 = out + ((size_t)b * T_ + r0 + g) * H_;
        float* orow1 = out + ((size_t)b * T_ + r0 + g + 8) * H_;
        #pragma unroll
        for (int nt = 0; nt < 8; nt++) {
            int n = nt * 8 + 2 * c4;
            *(float2*)&orow0[n] = make_float2(oacc[nt][0] * inv0, oacc[nt][1] * inv0);
            *(float2*)&orow1[n] = make_float2(oacc[nt][2] * inv1, oacc[nt][3] * inv1);
        }
    }
}

// ---------------------------------------------------------------------------
extern "C" void kernel_launch(void* const* d_in, const int* in_sizes, int n_in,
                              void* d_out, int out_size)
{
    const float* x  = (const float*)d_in[0];
    const float* Wq = (const float*)d_in[1];
    const float* Wk = (const float*)d_in[2];
    const float* Wv = (const float*)d_in[3];
    float* out = (float*)d_out;
    (void)in_sizes; (void)n_in; (void)out_size;

    wconv<<<(3 * EMB_ * H_ + 255) / 256, 256>>>(Wq, Wk, Wv);

    cudaFuncSetAttribute(qkv_mm, cudaFuncAttributeMaxDynamicSharedMemorySize, SMEM_SZ);
    qkv_mm<<<M_ / 128, 256, SMEM_SZ>>>(x);

    cudaFuncSetAttribute(attn_tc, cudaFuncAttributeMaxDynamicSharedMemorySize, ATTN_SMEM);
    attn_tc<<<B_, 256, ATTN_SMEM>>>(out);
}

// round 7
// speedup vs baseline: 5.3897x; 1.4713x over previous
#include <cuda_runtime.h>
#include <cuda_fp16.h>
#include <cuda_bf16.h>
#include <cstdint>

#define B_   256
#define T_   256
#define EMB_ 384
#define H_   64
#define M_   (B_*T_)

// Scratch: q,k,v projections [3][B*T][H], and fp16 weights [w][n][k]
__device__ float g_qkv[3][(size_t)M_ * H_];
__device__ __align__(16) __half g_wt[3][H_][EMB_];

#define SW128(o) ((o) ^ ((((uint32_t)(o)) >> 3) & 0x70))

__device__ __forceinline__ uint32_t smem_u32(const void* p) {
    uint32_t a;
    asm("{ .reg .u64 t; cvta.to.shared.u64 t, %1; cvt.u32.u64 %0, t; }"
        : "=r"(a) : "l"(p));
    return a;
}

__device__ __forceinline__ void ldsm4(uint32_t* r, uint32_t addr) {
    asm volatile("ldmatrix.sync.aligned.m8n8.x4.shared.b16 {%0,%1,%2,%3}, [%4];"
                 : "=r"(r[0]), "=r"(r[1]), "=r"(r[2]), "=r"(r[3]) : "r"(addr));
}

__device__ __forceinline__ void ldsm4t(uint32_t* r, uint32_t addr) {
    asm volatile("ldmatrix.sync.aligned.m8n8.x4.trans.shared.b16 {%0,%1,%2,%3}, [%4];"
                 : "=r"(r[0]), "=r"(r[1]), "=r"(r[2]), "=r"(r[3]) : "r"(addr));
}

// bf16 mma (attention)
__device__ __forceinline__ void mma16816(float* d, const uint32_t* a,
                                         uint32_t b0, uint32_t b1) {
    asm volatile(
        "mma.sync.aligned.m16n8k16.row.col.f32.bf16.bf16.f32 "
        "{%0,%1,%2,%3}, {%4,%5,%6,%7}, {%8,%9}, {%0,%1,%2,%3};"
        : "+f"(d[0]), "+f"(d[1]), "+f"(d[2]), "+f"(d[3])
        : "r"(a[0]), "r"(a[1]), "r"(a[2]), "r"(a[3]), "r"(b0), "r"(b1));
}

// fp16 mma (QKV projection)
__device__ __forceinline__ void mma16816h(float* d, const uint32_t* a,
                                          uint32_t b0, uint32_t b1) {
    asm volatile(
        "mma.sync.aligned.m16n8k16.row.col.f32.f16.f16.f32 "
        "{%0,%1,%2,%3}, {%4,%5,%6,%7}, {%8,%9}, {%0,%1,%2,%3};"
        : "+f"(d[0]), "+f"(d[1]), "+f"(d[2]), "+f"(d[3])
        : "r"(a[0]), "r"(a[1]), "r"(a[2]), "r"(a[3]), "r"(b0), "r"(b1));
}

__device__ __forceinline__ uint32_t pack_h2(float a, float b) {
    uint32_t r;
    asm("cvt.rn.f16x2.f32 %0, %1, %2;" : "=r"(r) : "f"(b), "f"(a));
    return r;
}

// bf16 hi/lo split (attention staging)
__device__ __forceinline__ void split2(float a, float b, uint32_t& hp, uint32_t& lp) {
    asm("cvt.rn.bf16x2.f32 %0, %1, %2;" : "=r"(hp) : "f"(b), "f"(a));
    float ha = __uint_as_float(hp << 16);
    float hb = __uint_as_float(hp & 0xffff0000u);
    float la = a - ha;
    float lb = b - hb;
    asm("cvt.rn.bf16x2.f32 %0, %1, %2;" : "=r"(lp) : "f"(lb), "f"(la));
}

__device__ __forceinline__ void cp_async16(uint32_t saddr, const void* g) {
    asm volatile("cp.async.cg.shared.global [%0], [%1], 16;" :: "r"(saddr), "l"(g));
}
#define CP_COMMIT() asm volatile("cp.async.commit_group;" ::: "memory")
#define CP_WAIT0()  asm volatile("cp.async.wait_group 0;" ::: "memory")

// ---------------------------------------------------------------------------
// Kernel 0: convert W to fp16, transposed to [n][k]. 4 k-elems/thread (MLP=4).
// ---------------------------------------------------------------------------
__global__ void wconv(const float* __restrict__ Wq, const float* __restrict__ Wk,
                      const float* __restrict__ Wv) {
    int idx = blockIdx.x * 256 + threadIdx.x;   // 3*64*96 = 18432 threads
    if (idx >= 3 * H_ * (EMB_ / 4)) return;
    int w  = idx / (H_ * (EMB_ / 4));
    int r  = idx % (H_ * (EMB_ / 4));
    int n  = r / (EMB_ / 4);
    int k4 = (r % (EMB_ / 4)) * 4;
    const float* W = (w == 0) ? Wq : (w == 1) ? Wk : Wv;
    float v0 = W[(k4 + 0) * H_ + n];
    float v1 = W[(k4 + 1) * H_ + n];
    float v2 = W[(k4 + 2) * H_ + n];
    float v3 = W[(k4 + 3) * H_ + n];
    uint2 p;
    p.x = pack_h2(v0, v1);
    p.y = pack_h2(v2, v3);
    *(uint2*)&g_wt[w][n][k4] = p;
}

// ---------------------------------------------------------------------------
// Kernel 1: QKV projection, single fp16 mma, software pipelined.
// 512 threads / 16 warps. CTA = 128 M-rows x 192 N.
// Warp w: rows ((w&7)*16 .. +16), cols ((w>>3)*96 .. +96)  [12 n-tiles of 8]
// smem: x fp16 2 stages x 16K at 0; W fp16 2 stages x 24K at 32768.
// ---------------------------------------------------------------------------
#define SM_W0    32768
#define SMEM_SZ  (SM_W0 + 2*24576)

__device__ __forceinline__ void ldg_x(float4* xr, const float* __restrict__ xb,
                                      int k0, int tid) {
    #pragma unroll
    for (int it = 0; it < 4; it++) {
        int f = tid + it * 512;
        xr[it] = *(const float4*)&xb[(size_t)(f >> 4) * EMB_ + k0 + (f & 15) * 4];
    }
}

__device__ __forceinline__ void sts_x(const float4* xr, char* xs, int tid) {
    #pragma unroll
    for (int it = 0; it < 4; it++) {
        int f = tid + it * 512;
        uint32_t off = SW128((f >> 4) * 128 + (f & 15) * 8);
        uint2 p;
        p.x = pack_h2(xr[it].x, xr[it].y);
        p.y = pack_h2(xr[it].z, xr[it].w);
        *(uint2*)(xs + off) = p;
    }
}

__device__ __forceinline__ void cp_w(uint32_t wdst, int k0, int tid) {
    #pragma unroll
    for (int it = 0; it < 3; it++) {
        int f  = tid + it * 512;     // 0..1535
        int w2 = f >> 9;
        int r  = f & 511;
        int n  = r >> 3;
        int q8 = r & 7;
        cp_async16(wdst + w2 * 8192 + SW128(n * 128 + q8 * 16),
                   &g_wt[w2][n][k0 + q8 * 8]);
    }
}

__global__ __launch_bounds__(512) void qkv_mm(const float* __restrict__ x)
{
    extern __shared__ char smem[];
    const uint32_t sb = smem_u32(smem);
    const int tid  = threadIdx.x;
    const int wid  = tid >> 5;
    const int lane = tid & 31;
    const int m0   = blockIdx.x * 128;
    const float* xb = x + (size_t)m0 * EMB_;

    const int wrow = wid & 7;          // row group
    const int hcol = wid >> 3;         // N-half (0: cols 0-95, 1: cols 96-191)

    float acc[12][4] = {};

    const int lrow   = (lane & 7) + ((lane >> 3) & 1) * 8;
    const int a_row  = wrow * 16 + lrow;
    const int a_colb = ((lane >> 4) & 1) * 16;
    const int b_n    = (lane >> 4) * 8 + (lane & 7);
    const int b_colb = ((lane >> 3) & 1) * 16;

    float4 xr[4];
    ldg_x(xr, xb, 0, tid);
    cp_w(sb + SM_W0, 0, tid);
    CP_COMMIT();

    #pragma unroll 1
    for (int c = 0; c < 6; c++) {
        const int st = c & 1;
        sts_x(xr, smem + st * 16384, tid);
        CP_WAIT0();
        __syncthreads();

        if (c < 5) {
            ldg_x(xr, xb, (c + 1) * 64, tid);
            cp_w(sb + SM_W0 + (st ^ 1) * 24576, (c + 1) * 64, tid);
            CP_COMMIT();
        }

        const uint32_t xs = sb + st * 16384;
        const uint32_t wbase = sb + SM_W0 + st * 24576;
        #pragma unroll
        for (int ks = 0; ks < 4; ks++) {
            uint32_t ah[4];
            ldsm4(ah, xs + SW128(a_row * 128 + ks * 32 + a_colb));
            #pragma unroll
            for (int np = 0; np < 6; np++) {
                const int colb = hcol * 96 + np * 16;
                const uint32_t wt = wbase + (colb >> 6) * 8192;
                const int nloc = colb & 63;
                uint32_t bb[4];
                ldsm4(bb, wt + SW128((nloc + b_n) * 128 + ks * 32 + b_colb));
                // Fragment map: bb[0]=n0-7/k0-7, bb[1]=n0-7/k8-15,
                //               bb[2]=n8-15/k0-7, bb[3]=n8-15/k8-15
                mma16816h(acc[2*np],   ah, bb[0], bb[1]);
                mma16816h(acc[2*np+1], ah, bb[2], bb[3]);
            }
        }
    }

    // epilogue
    const int g  = lane >> 2;
    const int c2 = (lane & 3) * 2;
    const int r0 = m0 + wrow * 16 + g;
    #pragma unroll
    for (int nt = 0; nt < 12; nt++) {
        int col = hcol * 96 + nt * 8 + c2;
        int w2  = col >> 6;
        int n   = col & 63;
        *(float2*)&g_qkv[w2][(size_t)r0 * H_ + n] =
            make_float2(acc[nt][0], acc[nt][1]);
        *(float2*)&g_qkv[w2][(size_t)(r0 + 8) * H_ + n] =
            make_float2(acc[nt][2], acc[nt][3]);
    }
}

// ---------------------------------------------------------------------------
// Kernel 2: tensor-core causal attention (bf16 3-term, unchanged from R5).
// smem: Khi 0, Klo 32K, Vhi 64K, Vlo 96K  (128 KB)
// ---------------------------------------------------------------------------
#define ATTN_SMEM 131072

__global__ __launch_bounds__(256) void attn_tc(float* __restrict__ out)
{
    extern __shared__ char smem[];
    const uint32_t sb = smem_u32(smem);
    const int b    = blockIdx.x;
    const int tid  = threadIdx.x;
    const int wid  = tid >> 5;
    const int lane = tid & 31;

    const float* qq = g_qkv[0] + (size_t)b * T_ * H_;
    const float* kk = g_qkv[1] + (size_t)b * T_ * H_;
    const float* vv = g_qkv[2] + (size_t)b * T_ * H_;

    char* khp = smem;
    char* klp = smem + 32768;
    char* vhp = smem + 65536;
    char* vlp = smem + 98304;
    #pragma unroll
    for (int it = 0; it < 16; it++) {
        int f  = tid + it * 256;
        int j  = f >> 4;
        int h0 = (f & 15) * 4;
        uint32_t off = SW128(j * 128 + h0 * 2);
        float4 a = *(const float4*)&kk[(size_t)j * H_ + h0];
        uint2 hp, lp;
        split2(a.x, a.y, hp.x, lp.x);
        split2(a.z, a.w, hp.y, lp.y);
        *(uint2*)(khp + off) = hp;
        *(uint2*)(klp + off) = lp;
        float4 c = *(const float4*)&vv[(size_t)j * H_ + h0];
        split2(c.x, c.y, hp.x, lp.x);
        split2(c.z, c.w, hp.y, lp.y);
        *(uint2*)(vhp + off) = hp;
        *(uint2*)(vlp + off) = lp;
    }
    __syncthreads();

    const float scale_l2e = 0.05103103630798287f * 1.4426950408889634f;
    const int g  = lane >> 2;
    const int c4 = lane & 3;
    const int lrow  = (lane & 7) + ((lane >> 3) & 1) * 8;
    const int lcolh = ((lane >> 4) & 1) * 16;

    const uint32_t kh = sb;
    const uint32_t kl = sb + 32768;
    const uint32_t vh = sb + 65536;
    const uint32_t vl = sb + 98304;

    #pragma unroll 1
    for (int half = 0; half < 2; half++) {
        const int tt = (half == 0) ? wid : 15 - wid;
        const int r0 = tt * 16;

        uint32_t qfh[4][4], qfl[4][4];
        #pragma unroll
        for (int kc = 0; kc < 4; kc++) {
            #pragma unroll
            for (int rr = 0; rr < 4; rr++) {
                int row = r0 + g + (rr & 1) * 8;
                int col = kc * 16 + (rr >> 1) * 8 + 2 * c4;
                float2 v = *(const float2*)&qq[(size_t)row * H_ + col];
                v.x *= scale_l2e;  v.y *= scale_l2e;
                split2(v.x, v.y, qfh[kc][rr], qfl[kc][rr]);
            }
        }

        float oacc[8][4] = {};
        float sum0 = 0.0f, sum1 = 0.0f;
        const int nb = (r0 + 47) >> 5;

        #pragma unroll 1
        for (int blk = 0; blk < nb; blk++) {
            const int s0 = blk * 32;
            float sacc[4][4] = {};

            #pragma unroll
            for (int kc = 0; kc < 4; kc++) {
                uint32_t bh[8], bl[8];
                #pragma unroll
                for (int grp = 0; grp < 2; grp++) {
                    uint32_t off = SW128((s0 + grp * 16 + lrow) * 128 + kc * 32 + lcolh);
                    ldsm4(&bh[grp * 4], kh + off);
                    ldsm4(&bl[grp * 4], kl + off);
                }
                #pragma unroll
                for (int nt = 0; nt < 4; nt++) {
                    const int base = (nt >> 1) * 4;
                    const uint32_t b0h = bh[base + (nt & 1)];
                    const uint32_t b1h = bh[base + (nt & 1) + 2];
                    const uint32_t b0l = bl[base + (nt & 1)];
                    const uint32_t b1l = bl[base + (nt & 1) + 2];
                    mma16816(sacc[nt], qfh[kc], b0h, b1h);
                    mma16816(sacc[nt], qfh[kc], b0l, b1l);
                    mma16816(sacc[nt], qfl[kc], b0h, b1h);
                }
            }

            const bool last = (blk == nb - 1);
            float p[4][4];
            #pragma unroll
            for (int nt = 0; nt < 4; nt++) {
                #pragma unroll
                for (int rr = 0; rr < 4; rr++) {
                    int j = s0 + nt * 8 + 2 * c4 + (rr & 1);
                    int t = r0 + g + (rr >> 1) * 8;
                    float e = (!last || j <= t) ? exp2f(sacc[nt][rr]) : 0.0f;
                    p[nt][rr] = e;
                    if (rr < 2) sum0 += e; else sum1 += e;
                }
            }

            uint32_t pfh[2][4], pfl[2][4];
            #pragma unroll
            for (int kc2 = 0; kc2 < 2; kc2++) {
                const float* p0 = p[2 * kc2];
                const float* p1 = p[2 * kc2 + 1];
                split2(p0[0], p0[1], pfh[kc2][0], pfl[kc2][0]);
                split2(p0[2], p0[3], pfh[kc2][1], pfl[kc2][1]);
                split2(p1[0], p1[1], pfh[kc2][2], pfl[kc2][2]);
                split2(p1[2], p1[3], pfh[kc2][3], pfl[kc2][3]);
            }

            #pragma unroll
            for (int kc2 = 0; kc2 < 2; kc2++) {
                #pragma unroll
                for (int np = 0; np < 4; np++) {
                    uint32_t off = SW128((s0 + kc2 * 16 + lrow) * 128 + np * 32 + lcolh);
                    uint32_t vbh[4], vbl[4];
                    ldsm4t(vbh, vh + off);
                    ldsm4t(vbl, vl + off);
                    mma16816(oacc[2*np],   pfh[kc2], vbh[0], vbh[1]);
                    mma16816(oacc[2*np],   pfh[kc2], vbl[0], vbl[1]);
                    mma16816(oacc[2*np],   pfl[kc2], vbh[0], vbh[1]);
                    mma16816(oacc[2*np+1], pfh[kc2], vbh[2], vbh[3]);
                    mma16816(oacc[2*np+1], pfh[kc2], vbl[2], vbl[3]);
                    mma16816(oacc[2*np+1], pfl[kc2], vbh[2], vbh[3]);
                }
            }
        }

        sum0 += __shfl_xor_sync(0xffffffffu, sum0, 1);
        sum0 += __shfl_xor_sync(0xffffffffu, sum0, 2);
        sum1 += __shfl_xor_sync(0xffffffffu, sum1, 1);
        sum1 += __shfl_xor_sync(0xffffffffu, sum1, 2);
        const float inv0 = 1.0f / sum0;
        const float inv1 = 1.0f / sum1;

        float* orow0 = out + ((size_t)b * T_ + r0 + g) * H_;
        float* orow1 = out + ((size_t)b * T_ + r0 + g + 8) * H_;
        #pragma unroll
        for (int nt = 0; nt < 8; nt++) {
            int n = nt * 8 + 2 * c4;
            *(float2*)&orow0[n] = make_float2(oacc[nt][0] * inv0, oacc[nt][1] * inv0);
            *(float2*)&orow1[n] = make_float2(oacc[nt][2] * inv1, oacc[nt][3] * inv1);
        }
    }
}

// ---------------------------------------------------------------------------
extern "C" void kernel_launch(void* const* d_in, const int* in_sizes, int n_in,
                              void* d_out, int out_size)
{
    const float* x  = (const float*)d_in[0];
    const float* Wq = (const float*)d_in[1];
    const float* Wk = (const float*)d_in[2];
    const float* Wv = (const float*)d_in[3];
    float* out = (float*)d_out;
    (void)in_sizes; (void)n_in; (void)out_size;

    wconv<<<(3 * H_ * (EMB_ / 4) + 255) / 256, 256>>>(Wq, Wk, Wv);

    cudaFuncSetAttribute(qkv_mm, cudaFuncAttributeMaxDynamicSharedMemorySize, SMEM_SZ);
    qkv_mm<<<M_ / 128, 512, SMEM_SZ>>>(x);

    cudaFuncSetAttribute(attn_tc, cudaFuncAttributeMaxDynamicSharedMemorySize, ATTN_SMEM);
    attn_tc<<<B_, 256, ATTN_SMEM>>>(out);
}

// round 8
// speedup vs baseline: 6.6550x; 1.2348x over previous
#include <cuda_runtime.h>
#include <cuda_fp16.h>
#include <cstdint>

#define B_   256
#define T_   256
#define EMB_ 384
#define H_   64
#define M_   (B_*T_)

// Scratch: q,k,v projections [3][B*T][H], and fp16 weights [w][n][k]
__device__ float g_qkv[3][(size_t)M_ * H_];
__device__ __align__(16) __half g_wt[3][H_][EMB_];

#define SW128(o) ((o) ^ ((((uint32_t)(o)) >> 3) & 0x70))

__device__ __forceinline__ uint32_t smem_u32(const void* p) {
    uint32_t a;
    asm("{ .reg .u64 t; cvta.to.shared.u64 t, %1; cvt.u32.u64 %0, t; }"
        : "=r"(a) : "l"(p));
    return a;
}

__device__ __forceinline__ void ldsm4(uint32_t* r, uint32_t addr) {
    asm volatile("ldmatrix.sync.aligned.m8n8.x4.shared.b16 {%0,%1,%2,%3}, [%4];"
                 : "=r"(r[0]), "=r"(r[1]), "=r"(r[2]), "=r"(r[3]) : "r"(addr));
}

__device__ __forceinline__ void ldsm4t(uint32_t* r, uint32_t addr) {
    asm volatile("ldmatrix.sync.aligned.m8n8.x4.trans.shared.b16 {%0,%1,%2,%3}, [%4];"
                 : "=r"(r[0]), "=r"(r[1]), "=r"(r[2]), "=r"(r[3]) : "r"(addr));
}

// fp16 mma
__device__ __forceinline__ void mma16816h(float* d, const uint32_t* a,
                                          uint32_t b0, uint32_t b1) {
    asm volatile(
        "mma.sync.aligned.m16n8k16.row.col.f32.f16.f16.f32 "
        "{%0,%1,%2,%3}, {%4,%5,%6,%7}, {%8,%9}, {%0,%1,%2,%3};"
        : "+f"(d[0]), "+f"(d[1]), "+f"(d[2]), "+f"(d[3])
        : "r"(a[0]), "r"(a[1]), "r"(a[2]), "r"(a[3]), "r"(b0), "r"(b1));
}

__device__ __forceinline__ uint32_t pack_h2(float a, float b) {
    uint32_t r;
    asm("cvt.rn.f16x2.f32 %0, %1, %2;" : "=r"(r) : "f"(b), "f"(a));
    return r;
}

__device__ __forceinline__ void cp_async16(uint32_t saddr, const void* g) {
    asm volatile("cp.async.cg.shared.global [%0], [%1], 16;" :: "r"(saddr), "l"(g));
}
#define CP_COMMIT() asm volatile("cp.async.commit_group;" ::: "memory")
#define CP_WAIT0()  asm volatile("cp.async.wait_group 0;" ::: "memory")

// ---------------------------------------------------------------------------
// Kernel 0: convert W to fp16, transposed to [n][k]. 4 k-elems/thread.
// ---------------------------------------------------------------------------
__global__ void wconv(const float* __restrict__ Wq, const float* __restrict__ Wk,
                      const float* __restrict__ Wv) {
    int idx = blockIdx.x * 256 + threadIdx.x;
    if (idx >= 3 * H_ * (EMB_ / 4)) return;
    int w  = idx / (H_ * (EMB_ / 4));
    int r  = idx % (H_ * (EMB_ / 4));
    int n  = r / (EMB_ / 4);
    int k4 = (r % (EMB_ / 4)) * 4;
    const float* W = (w == 0) ? Wq : (w == 1) ? Wk : Wv;
    float v0 = W[(k4 + 0) * H_ + n];
    float v1 = W[(k4 + 1) * H_ + n];
    float v2 = W[(k4 + 2) * H_ + n];
    float v3 = W[(k4 + 3) * H_ + n];
    uint2 p;
    p.x = pack_h2(v0, v1);
    p.y = pack_h2(v2, v3);
    *(uint2*)&g_wt[w][n][k4] = p;
}

// ---------------------------------------------------------------------------
// Kernel 1: QKV projection, single fp16 mma, software pipelined (R7).
// ---------------------------------------------------------------------------
#define SM_W0    32768
#define SMEM_SZ  (SM_W0 + 2*24576)

__device__ __forceinline__ void ldg_x(float4* xr, const float* __restrict__ xb,
                                      int k0, int tid) {
    #pragma unroll
    for (int it = 0; it < 4; it++) {
        int f = tid + it * 512;
        xr[it] = *(const float4*)&xb[(size_t)(f >> 4) * EMB_ + k0 + (f & 15) * 4];
    }
}

__device__ __forceinline__ void sts_x(const float4* xr, char* xs, int tid) {
    #pragma unroll
    for (int it = 0; it < 4; it++) {
        int f = tid + it * 512;
        uint32_t off = SW128((f >> 4) * 128 + (f & 15) * 8);
        uint2 p;
        p.x = pack_h2(xr[it].x, xr[it].y);
        p.y = pack_h2(xr[it].z, xr[it].w);
        *(uint2*)(xs + off) = p;
    }
}

__device__ __forceinline__ void cp_w(uint32_t wdst, int k0, int tid) {
    #pragma unroll
    for (int it = 0; it < 3; it++) {
        int f  = tid + it * 512;
        int w2 = f >> 9;
        int r  = f & 511;
        int n  = r >> 3;
        int q8 = r & 7;
        cp_async16(wdst + w2 * 8192 + SW128(n * 128 + q8 * 16),
                   &g_wt[w2][n][k0 + q8 * 8]);
    }
}

__global__ __launch_bounds__(512) void qkv_mm(const float* __restrict__ x)
{
    extern __shared__ char smem[];
    const uint32_t sb = smem_u32(smem);
    const int tid  = threadIdx.x;
    const int wid  = tid >> 5;
    const int lane = tid & 31;
    const int m0   = blockIdx.x * 128;
    const float* xb = x + (size_t)m0 * EMB_;

    const int wrow = wid & 7;
    const int hcol = wid >> 3;

    float acc[12][4] = {};

    const int lrow   = (lane & 7) + ((lane >> 3) & 1) * 8;
    const int a_row  = wrow * 16 + lrow;
    const int a_colb = ((lane >> 4) & 1) * 16;
    const int b_n    = (lane >> 4) * 8 + (lane & 7);
    const int b_colb = ((lane >> 3) & 1) * 16;

    float4 xr[4];
    ldg_x(xr, xb, 0, tid);
    cp_w(sb + SM_W0, 0, tid);
    CP_COMMIT();

    #pragma unroll 1
    for (int c = 0; c < 6; c++) {
        const int st = c & 1;
        sts_x(xr, smem + st * 16384, tid);
        CP_WAIT0();
        __syncthreads();

        if (c < 5) {
            ldg_x(xr, xb, (c + 1) * 64, tid);
            cp_w(sb + SM_W0 + (st ^ 1) * 24576, (c + 1) * 64, tid);
            CP_COMMIT();
        }

        const uint32_t xs = sb + st * 16384;
        const uint32_t wbase = sb + SM_W0 + st * 24576;
        #pragma unroll
        for (int ks = 0; ks < 4; ks++) {
            uint32_t ah[4];
            ldsm4(ah, xs + SW128(a_row * 128 + ks * 32 + a_colb));
            #pragma unroll
            for (int np = 0; np < 6; np++) {
                const int colb = hcol * 96 + np * 16;
                const uint32_t wt = wbase + (colb >> 6) * 8192;
                const int nloc = colb & 63;
                uint32_t bb[4];
                ldsm4(bb, wt + SW128((nloc + b_n) * 128 + ks * 32 + b_colb));
                mma16816h(acc[2*np],   ah, bb[0], bb[1]);
                mma16816h(acc[2*np+1], ah, bb[2], bb[3]);
            }
        }
    }

    const int g  = lane >> 2;
    const int c2 = (lane & 3) * 2;
    const int r0 = m0 + wrow * 16 + g;
    #pragma unroll
    for (int nt = 0; nt < 12; nt++) {
        int col = hcol * 96 + nt * 8 + c2;
        int w2  = col >> 6;
        int n   = col & 63;
        *(float2*)&g_qkv[w2][(size_t)r0 * H_ + n] =
            make_float2(acc[nt][0], acc[nt][1]);
        *(float2*)&g_qkv[w2][(size_t)(r0 + 8) * H_ + n] =
            make_float2(acc[nt][2], acc[nt][3]);
    }
}

// ---------------------------------------------------------------------------
// Kernel 2: tensor-core causal attention, all fp16 single-term.
// CTA = 1 batch, 8 warps. smem: K fp16 at 0 (32K), V fp16 at 32K. 64 KB total
// -> 2 CTAs/SM. No max-subtraction; exp2 with log2e folded into Q scale.
// ---------------------------------------------------------------------------
#define ATTN_SMEM 65536

__global__ __launch_bounds__(256) void attn_tc(float* __restrict__ out)
{
    extern __shared__ char smem[];
    const uint32_t sb = smem_u32(smem);
    const int b    = blockIdx.x;
    const int tid  = threadIdx.x;
    const int wid  = tid >> 5;
    const int lane = tid & 31;

    const float* qq = g_qkv[0] + (size_t)b * T_ * H_;
    const float* kk = g_qkv[1] + (size_t)b * T_ * H_;
    const float* vv = g_qkv[2] + (size_t)b * T_ * H_;

    char* kp = smem;
    char* vp = smem + 32768;
    #pragma unroll
    for (int it = 0; it < 16; it++) {
        int f  = tid + it * 256;
        int j  = f >> 4;
        int h0 = (f & 15) * 4;
        uint32_t off = SW128(j * 128 + h0 * 2);
        float4 a = *(const float4*)&kk[(size_t)j * H_ + h0];
        uint2 p;
        p.x = pack_h2(a.x, a.y);
        p.y = pack_h2(a.z, a.w);
        *(uint2*)(kp + off) = p;
        float4 c = *(const float4*)&vv[(size_t)j * H_ + h0];
        p.x = pack_h2(c.x, c.y);
        p.y = pack_h2(c.z, c.w);
        *(uint2*)(vp + off) = p;
    }
    __syncthreads();

    // 384^-0.5 * log2(e)
    const float scale_l2e = 0.05103103630798287f * 1.4426950408889634f;
    const int g  = lane >> 2;
    const int c4 = lane & 3;
    const int lrow  = (lane & 7) + ((lane >> 3) & 1) * 8;
    const int lcolh = ((lane >> 4) & 1) * 16;

    const uint32_t kbase = sb;
    const uint32_t vbase = sb + 32768;

    #pragma unroll 1
    for (int half = 0; half < 2; half++) {
        const int tt = (half == 0) ? wid : 15 - wid;
        const int r0 = tt * 16;

        // Q fragments, fp16, scale folded in
        uint32_t qf[4][4];
        #pragma unroll
        for (int kc = 0; kc < 4; kc++) {
            #pragma unroll
            for (int rr = 0; rr < 4; rr++) {
                int row = r0 + g + (rr & 1) * 8;
                int col = kc * 16 + (rr >> 1) * 8 + 2 * c4;
                float2 v = *(const float2*)&qq[(size_t)row * H_ + col];
                qf[kc][rr] = pack_h2(v.x * scale_l2e, v.y * scale_l2e);
            }
        }

        float oacc[8][4] = {};
        float sum0 = 0.0f, sum1 = 0.0f;
        const int nb = (r0 + 47) >> 5;

        #pragma unroll 1
        for (int blk = 0; blk < nb; blk++) {
            const int s0 = blk * 32;
            float sacc[4][4] = {};

            // ---- S = Q K^T over this 32-col block ----
            #pragma unroll
            for (int kc = 0; kc < 4; kc++) {
                uint32_t bh[8];
                #pragma unroll
                for (int grp = 0; grp < 2; grp++) {
                    uint32_t off = SW128((s0 + grp * 16 + lrow) * 128 + kc * 32 + lcolh);
                    ldsm4(&bh[grp * 4], kbase + off);
                }
                #pragma unroll
                for (int nt = 0; nt < 4; nt++) {
                    const int base = (nt >> 1) * 4;
                    mma16816h(sacc[nt], qf[kc],
                              bh[base + (nt & 1)], bh[base + (nt & 1) + 2]);
                }
            }

            // ---- exp2 + causal mask + rowsum ----
            const bool last = (blk == nb - 1);
            float p[4][4];
            #pragma unroll
            for (int nt = 0; nt < 4; nt++) {
                #pragma unroll
                for (int rr = 0; rr < 4; rr++) {
                    int j = s0 + nt * 8 + 2 * c4 + (rr & 1);
                    int t = r0 + g + (rr >> 1) * 8;
                    float e = (!last || j <= t) ? exp2f(sacc[nt][rr]) : 0.0f;
                    p[nt][rr] = e;
                    if (rr < 2) sum0 += e; else sum1 += e;
                }
            }

            // ---- P fragments, fp16 ----
            uint32_t pf[2][4];
            #pragma unroll
            for (int kc2 = 0; kc2 < 2; kc2++) {
                const float* p0 = p[2 * kc2];
                const float* p1 = p[2 * kc2 + 1];
                pf[kc2][0] = pack_h2(p0[0], p0[1]);
                pf[kc2][1] = pack_h2(p0[2], p0[3]);
                pf[kc2][2] = pack_h2(p1[0], p1[1]);
                pf[kc2][3] = pack_h2(p1[2], p1[3]);
            }

            // ---- O += P V ----
            #pragma unroll
            for (int kc2 = 0; kc2 < 2; kc2++) {
                #pragma unroll
                for (int np = 0; np < 4; np++) {
                    uint32_t off = SW128((s0 + kc2 * 16 + lrow) * 128 + np * 32 + lcolh);
                    uint32_t vb[4];
                    ldsm4t(vb, vbase + off);
                    mma16816h(oacc[2*np],   pf[kc2], vb[0], vb[1]);
                    mma16816h(oacc[2*np+1], pf[kc2], vb[2], vb[3]);
                }
            }
        }

        // ---- rowsum reduce, scale, store ----
        sum0 += __shfl_xor_sync(0xffffffffu, sum0, 1);
        sum0 += __shfl_xor_sync(0xffffffffu, sum0, 2);
        sum1 += __shfl_xor_sync(0xffffffffu, sum1, 1);
        sum1 += __shfl_xor_sync(0xffffffffu, sum1, 2);
        const float inv0 = 1.0f / sum0;
        const float inv1 = 1.0f / sum1;

        float* orow0 = out + ((size_t)b * T_ + r0 + g) * H_;
        float* orow1 = out + ((size_t)b * T_ + r0 + g + 8) * H_;
        #pragma unroll
        for (int nt = 0; nt < 8; nt++) {
            int n = nt * 8 + 2 * c4;
            *(float2*)&orow0[n] = make_float2(oacc[nt][0] * inv0, oacc[nt][1] * inv0);
            *(float2*)&orow1[n] = make_float2(oacc[nt][2] * inv1, oacc[nt][3] * inv1);
        }
    }
}

// ---------------------------------------------------------------------------
extern "C" void kernel_launch(void* const* d_in, const int* in_sizes, int n_in,
                              void* d_out, int out_size)
{
    const float* x  = (const float*)d_in[0];
    const float* Wq = (const float*)d_in[1];
    const float* Wk = (const float*)d_in[2];
    const float* Wv = (const float*)d_in[3];
    float* out = (float*)d_out;
    (void)in_sizes; (void)n_in; (void)out_size;

    wconv<<<(3 * H_ * (EMB_ / 4) + 255) / 256, 256>>>(Wq, Wk, Wv);

    cudaFuncSetAttribute(qkv_mm, cudaFuncAttributeMaxDynamicSharedMemorySize, SMEM_SZ);
    qkv_mm<<<M_ / 128, 512, SMEM_SZ>>>(x);

    cudaFuncSetAttribute(attn_tc, cudaFuncAttributeMaxDynamicSharedMemorySize, ATTN_SMEM);
    attn_tc<<<B_, 256, ATTN_SMEM>>>(out);
}

// round 9
// speedup vs baseline: 6.7641x; 1.0164x over previous
#include <cuda_runtime.h>
#include <cuda_fp16.h>
#include <cstdint>

#define B_   256
#define T_   256
#define EMB_ 384
#define H_   64
#define M_   (B_*T_)

// Scratch: q,k,v projections in fp16 (q pre-scaled by 384^-.5*log2e), and
// fp16 weights [w][n][k] (Wq pre-scaled likewise).
__device__ __align__(16) __half g_qkv[3][(size_t)M_ * H_];
__device__ __align__(16) __half g_wt[3][H_][EMB_];

#define SW128(o) ((o) ^ ((((uint32_t)(o)) >> 3) & 0x70))

__device__ __forceinline__ uint32_t smem_u32(const void* p) {
    uint32_t a;
    asm("{ .reg .u64 t; cvta.to.shared.u64 t, %1; cvt.u32.u64 %0, t; }"
        : "=r"(a) : "l"(p));
    return a;
}

__device__ __forceinline__ void ldsm4(uint32_t* r, uint32_t addr) {
    asm volatile("ldmatrix.sync.aligned.m8n8.x4.shared.b16 {%0,%1,%2,%3}, [%4];"
                 : "=r"(r[0]), "=r"(r[1]), "=r"(r[2]), "=r"(r[3]) : "r"(addr));
}

__device__ __forceinline__ void ldsm4t(uint32_t* r, uint32_t addr) {
    asm volatile("ldmatrix.sync.aligned.m8n8.x4.trans.shared.b16 {%0,%1,%2,%3}, [%4];"
                 : "=r"(r[0]), "=r"(r[1]), "=r"(r[2]), "=r"(r[3]) : "r"(addr));
}

__device__ __forceinline__ void mma16816h(float* d, const uint32_t* a,
                                          uint32_t b0, uint32_t b1) {
    asm volatile(
        "mma.sync.aligned.m16n8k16.row.col.f32.f16.f16.f32 "
        "{%0,%1,%2,%3}, {%4,%5,%6,%7}, {%8,%9}, {%0,%1,%2,%3};"
        : "+f"(d[0]), "+f"(d[1]), "+f"(d[2]), "+f"(d[3])
        : "r"(a[0]), "r"(a[1]), "r"(a[2]), "r"(a[3]), "r"(b0), "r"(b1));
}

__device__ __forceinline__ uint32_t pack_h2(float a, float b) {
    uint32_t r;
    asm("cvt.rn.f16x2.f32 %0, %1, %2;" : "=r"(r) : "f"(b), "f"(a));
    return r;
}

__device__ __forceinline__ void cp_async16(uint32_t saddr, const void* g) {
    asm volatile("cp.async.cg.shared.global [%0], [%1], 16;" :: "r"(saddr), "l"(g));
}
#define CP_COMMIT() asm volatile("cp.async.commit_group;" ::: "memory")
#define CP_WAIT0()  asm volatile("cp.async.wait_group 0;" ::: "memory")

// ---------------------------------------------------------------------------
// Kernel 0: W -> fp16, transposed to [n][k]; Wq pre-scaled by 384^-.5*log2e.
// ---------------------------------------------------------------------------
__global__ void wconv(const float* __restrict__ Wq, const float* __restrict__ Wk,
                      const float* __restrict__ Wv) {
    int idx = blockIdx.x * 256 + threadIdx.x;
    if (idx >= 3 * H_ * (EMB_ / 4)) return;
    int w  = idx / (H_ * (EMB_ / 4));
    int r  = idx % (H_ * (EMB_ / 4));
    int n  = r / (EMB_ / 4);
    int k4 = (r % (EMB_ / 4)) * 4;
    const float* W = (w == 0) ? Wq : (w == 1) ? Wk : Wv;
    // q scale * log2(e) folded into Wq
    const float s = (w == 0) ? 0.05103103630798287f * 1.4426950408889634f : 1.0f;
    float v0 = W[(k4 + 0) * H_ + n] * s;
    float v1 = W[(k4 + 1) * H_ + n] * s;
    float v2 = W[(k4 + 2) * H_ + n] * s;
    float v3 = W[(k4 + 3) * H_ + n] * s;
    uint2 p;
    p.x = pack_h2(v0, v1);
    p.y = pack_h2(v2, v3);
    *(uint2*)&g_wt[w][n][k4] = p;
}

// ---------------------------------------------------------------------------
// Kernel 1: QKV projection, single fp16 mma, software pipelined.
// Epilogue now packs to fp16 and writes uint32 (half the store traffic).
// ---------------------------------------------------------------------------
#define SM_W0    32768
#define SMEM_SZ  (SM_W0 + 2*24576)

__device__ __forceinline__ void ldg_x(float4* xr, const float* __restrict__ xb,
                                      int k0, int tid) {
    #pragma unroll
    for (int it = 0; it < 4; it++) {
        int f = tid + it * 512;
        xr[it] = *(const float4*)&xb[(size_t)(f >> 4) * EMB_ + k0 + (f & 15) * 4];
    }
}

__device__ __forceinline__ void sts_x(const float4* xr, char* xs, int tid) {
    #pragma unroll
    for (int it = 0; it < 4; it++) {
        int f = tid + it * 512;
        uint32_t off = SW128((f >> 4) * 128 + (f & 15) * 8);
        uint2 p;
        p.x = pack_h2(xr[it].x, xr[it].y);
        p.y = pack_h2(xr[it].z, xr[it].w);
        *(uint2*)(xs + off) = p;
    }
}

__device__ __forceinline__ void cp_w(uint32_t wdst, int k0, int tid) {
    #pragma unroll
    for (int it = 0; it < 3; it++) {
        int f  = tid + it * 512;
        int w2 = f >> 9;
        int r  = f & 511;
        int n  = r >> 3;
        int q8 = r & 7;
        cp_async16(wdst + w2 * 8192 + SW128(n * 128 + q8 * 16),
                   &g_wt[w2][n][k0 + q8 * 8]);
    }
}

__global__ __launch_bounds__(512) void qkv_mm(const float* __restrict__ x)
{
    extern __shared__ char smem[];
    const uint32_t sb = smem_u32(smem);
    const int tid  = threadIdx.x;
    const int wid  = tid >> 5;
    const int lane = tid & 31;
    const int m0   = blockIdx.x * 128;
    const float* xb = x + (size_t)m0 * EMB_;

    const int wrow = wid & 7;
    const int hcol = wid >> 3;

    float acc[12][4] = {};

    const int lrow   = (lane & 7) + ((lane >> 3) & 1) * 8;
    const int a_row  = wrow * 16 + lrow;
    const int a_colb = ((lane >> 4) & 1) * 16;
    const int b_n    = (lane >> 4) * 8 + (lane & 7);
    const int b_colb = ((lane >> 3) & 1) * 16;

    float4 xr[4];
    ldg_x(xr, xb, 0, tid);
    cp_w(sb + SM_W0, 0, tid);
    CP_COMMIT();

    #pragma unroll 1
    for (int c = 0; c < 6; c++) {
        const int st = c & 1;
        sts_x(xr, smem + st * 16384, tid);
        CP_WAIT0();
        __syncthreads();

        if (c < 5) {
            ldg_x(xr, xb, (c + 1) * 64, tid);
            cp_w(sb + SM_W0 + (st ^ 1) * 24576, (c + 1) * 64, tid);
            CP_COMMIT();
        }

        const uint32_t xs = sb + st * 16384;
        const uint32_t wbase = sb + SM_W0 + st * 24576;
        #pragma unroll
        for (int ks = 0; ks < 4; ks++) {
            uint32_t ah[4];
            ldsm4(ah, xs + SW128(a_row * 128 + ks * 32 + a_colb));
            #pragma unroll
            for (int np = 0; np < 6; np++) {
                const int colb = hcol * 96 + np * 16;
                const uint32_t wt = wbase + (colb >> 6) * 8192;
                const int nloc = colb & 63;
                uint32_t bb[4];
                ldsm4(bb, wt + SW128((nloc + b_n) * 128 + ks * 32 + b_colb));
                mma16816h(acc[2*np],   ah, bb[0], bb[1]);
                mma16816h(acc[2*np+1], ah, bb[2], bb[3]);
            }
        }
    }

    // epilogue: pack fp16, store uint32 per 2 cols
    const int g  = lane >> 2;
    const int c2 = (lane & 3) * 2;
    const int r0 = m0 + wrow * 16 + g;
    #pragma unroll
    for (int nt = 0; nt < 12; nt++) {
        int col = hcol * 96 + nt * 8 + c2;
        int w2  = col >> 6;
        int n   = col & 63;
        *(uint32_t*)&g_qkv[w2][(size_t)r0 * H_ + n] =
            pack_h2(acc[nt][0], acc[nt][1]);
        *(uint32_t*)&g_qkv[w2][(size_t)(r0 + 8) * H_ + n] =
            pack_h2(acc[nt][2], acc[nt][3]);
    }
}

// ---------------------------------------------------------------------------
// Kernel 2: fp16 tensor-core causal attention.
// K/V staged via cp.async (already fp16); Q fragments loaded directly from
// global (pre-scaled). smem: K 32K at 0, V 32K at 32768.
// ---------------------------------------------------------------------------
#define ATTN_SMEM 65536

__global__ __launch_bounds__(256) void attn_tc(float* __restrict__ out)
{
    extern __shared__ char smem[];
    const uint32_t sb = smem_u32(smem);
    const int b    = blockIdx.x;
    const int tid  = threadIdx.x;
    const int wid  = tid >> 5;
    const int lane = tid & 31;

    const __half* qh = g_qkv[0] + (size_t)b * T_ * H_;
    const __half* kh = g_qkv[1] + (size_t)b * T_ * H_;
    const __half* vh = g_qkv[2] + (size_t)b * T_ * H_;

    // Stage K and V via cp.async: 256 rows x 8 x 16B chunks each.
    #pragma unroll
    for (int it = 0; it < 8; it++) {
        int f  = tid + it * 256;     // 0..2047
        int j  = f >> 3;
        int q8 = f & 7;
        uint32_t off = SW128(j * 128 + q8 * 16);
        cp_async16(sb + off,         &kh[(size_t)j * H_ + q8 * 8]);
        cp_async16(sb + 32768 + off, &vh[(size_t)j * H_ + q8 * 8]);
    }
    CP_COMMIT();
    CP_WAIT0();
    __syncthreads();

    const int g  = lane >> 2;
    const int c4 = lane & 3;
    const int lrow  = (lane & 7) + ((lane >> 3) & 1) * 8;
    const int lcolh = ((lane >> 4) & 1) * 16;

    const uint32_t kbase = sb;
    const uint32_t vbase = sb + 32768;

    #pragma unroll 1
    for (int half = 0; half < 2; half++) {
        const int tt = (half == 0) ? wid : 15 - wid;
        const int r0 = tt * 16;

        // Q fragments: direct 4-byte loads (pre-scaled fp16 pairs)
        uint32_t qf[4][4];
        #pragma unroll
        for (int kc = 0; kc < 4; kc++) {
            #pragma unroll
            for (int rr = 0; rr < 4; rr++) {
                int row = r0 + g + (rr & 1) * 8;
                int col = kc * 16 + (rr >> 1) * 8 + 2 * c4;
                qf[kc][rr] = *(const uint32_t*)&qh[(size_t)row * H_ + col];
            }
        }

        float oacc[8][4] = {};
        float sum0 = 0.0f, sum1 = 0.0f;
        const int nb = (r0 + 47) >> 5;

        #pragma unroll 1
        for (int blk = 0; blk < nb; blk++) {
            const int s0 = blk * 32;
            float sacc[4][4] = {};

            // ---- S = Q K^T ----
            #pragma unroll
            for (int kc = 0; kc < 4; kc++) {
                uint32_t bh[8];
                #pragma unroll
                for (int grp = 0; grp < 2; grp++) {
                    uint32_t off = SW128((s0 + grp * 16 + lrow) * 128 + kc * 32 + lcolh);
                    ldsm4(&bh[grp * 4], kbase + off);
                }
                #pragma unroll
                for (int nt = 0; nt < 4; nt++) {
                    const int base = (nt >> 1) * 4;
                    mma16816h(sacc[nt], qf[kc],
                              bh[base + (nt & 1)], bh[base + (nt & 1) + 2]);
                }
            }

            // ---- exp2 + causal mask + rowsum ----
            const bool last = (blk == nb - 1);
            float p[4][4];
            #pragma unroll
            for (int nt = 0; nt < 4; nt++) {
                #pragma unroll
                for (int rr = 0; rr < 4; rr++) {
                    int j = s0 + nt * 8 + 2 * c4 + (rr & 1);
                    int t = r0 + g + (rr >> 1) * 8;
                    float e = (!last || j <= t) ? exp2f(sacc[nt][rr]) : 0.0f;
                    p[nt][rr] = e;
                    if (rr < 2) sum0 += e; else sum1 += e;
                }
            }

            // ---- P fragments, fp16 ----
            uint32_t pf[2][4];
            #pragma unroll
            for (int kc2 = 0; kc2 < 2; kc2++) {
                const float* p0 = p[2 * kc2];
                const float* p1 = p[2 * kc2 + 1];
                pf[kc2][0] = pack_h2(p0[0], p0[1]);
                pf[kc2][1] = pack_h2(p0[2], p0[3]);
                pf[kc2][2] = pack_h2(p1[0], p1[1]);
                pf[kc2][3] = pack_h2(p1[2], p1[3]);
            }

            // ---- O += P V ----
            #pragma unroll
            for (int kc2 = 0; kc2 < 2; kc2++) {
                #pragma unroll
                for (int np = 0; np < 4; np++) {
                    uint32_t off = SW128((s0 + kc2 * 16 + lrow) * 128 + np * 32 + lcolh);
                    uint32_t vb[4];
                    ldsm4t(vb, vbase + off);
                    mma16816h(oacc[2*np],   pf[kc2], vb[0], vb[1]);
                    mma16816h(oacc[2*np+1], pf[kc2], vb[2], vb[3]);
                }
            }
        }

        // ---- rowsum reduce, scale, store ----
        sum0 += __shfl_xor_sync(0xffffffffu, sum0, 1);
        sum0 += __shfl_xor_sync(0xffffffffu, sum0, 2);
        sum1 += __shfl_xor_sync(0xffffffffu, sum1, 1);
        sum1 += __shfl_xor_sync(0xffffffffu, sum1, 2);
        const float inv0 = 1.0f / sum0;
        const float inv1 = 1.0f / sum1;

        float* orow0 = out + ((size_t)b * T_ + r0 + g) * H_;
        float* orow1 = out + ((size_t)b * T_ + r0 + g + 8) * H_;
        #pragma unroll
        for (int nt = 0; nt < 8; nt++) {
            int n = nt * 8 + 2 * c4;
            *(float2*)&orow0[n] = make_float2(oacc[nt][0] * inv0, oacc[nt][1] * inv0);
            *(float2*)&orow1[n] = make_float2(oacc[nt][2] * inv1, oacc[nt][3] * inv1);
        }
    }
}

// ---------------------------------------------------------------------------
extern "C" void kernel_launch(void* const* d_in, const int* in_sizes, int n_in,
                              void* d_out, int out_size)
{
    const float* x  = (const float*)d_in[0];
    const float* Wq = (const float*)d_in[1];
    const float* Wk = (const float*)d_in[2];
    const float* Wv = (const float*)d_in[3];
    float* out = (float*)d_out;
    (void)in_sizes; (void)n_in; (void)out_size;

    wconv<<<(3 * H_ * (EMB_ / 4) + 255) / 256, 256>>>(Wq, Wk, Wv);

    cudaFuncSetAttribute(qkv_mm, cudaFuncAttributeMaxDynamicSharedMemorySize, SMEM_SZ);
    qkv_mm<<<M_ / 128, 512, SMEM_SZ>>>(x);

    cudaFuncSetAttribute(attn_tc, cudaFuncAttributeMaxDynamicSharedMemorySize, ATTN_SMEM);
    attn_tc<<<B_, 256, ATTN_SMEM>>>(out);
}

// round 10
// speedup vs baseline: 7.1967x; 1.0640x over previous
#include <cuda_runtime.h>
#include <cuda_fp16.h>
#include <cstdint>

#define B_   256
#define T_   256
#define EMB_ 384
#define H_   64
#define M_   (B_*T_)

// Scratch: q,k,v projections in fp16 (q pre-scaled by 384^-.5*log2e), and
// fp16 weights [w][n][k] (Wq pre-scaled likewise).
__device__ __align__(16) __half g_qkv[3][(size_t)M_ * H_];
__device__ __align__(16) __half g_wt[3][H_][EMB_];

#define SW128(o) ((o) ^ ((((uint32_t)(o)) >> 3) & 0x70))

__device__ __forceinline__ uint32_t smem_u32(const void* p) {
    uint32_t a;
    asm("{ .reg .u64 t; cvta.to.shared.u64 t, %1; cvt.u32.u64 %0, t; }"
        : "=r"(a) : "l"(p));
    return a;
}

__device__ __forceinline__ void ldsm4(uint32_t* r, uint32_t addr) {
    asm volatile("ldmatrix.sync.aligned.m8n8.x4.shared.b16 {%0,%1,%2,%3}, [%4];"
                 : "=r"(r[0]), "=r"(r[1]), "=r"(r[2]), "=r"(r[3]) : "r"(addr));
}

__device__ __forceinline__ void ldsm4t(uint32_t* r, uint32_t addr) {
    asm volatile("ldmatrix.sync.aligned.m8n8.x4.trans.shared.b16 {%0,%1,%2,%3}, [%4];"
                 : "=r"(r[0]), "=r"(r[1]), "=r"(r[2]), "=r"(r[3]) : "r"(addr));
}

__device__ __forceinline__ void mma16816h(float* d, const uint32_t* a,
                                          uint32_t b0, uint32_t b1) {
    asm volatile(
        "mma.sync.aligned.m16n8k16.row.col.f32.f16.f16.f32 "
        "{%0,%1,%2,%3}, {%4,%5,%6,%7}, {%8,%9}, {%0,%1,%2,%3};"
        : "+f"(d[0]), "+f"(d[1]), "+f"(d[2]), "+f"(d[3])
        : "r"(a[0]), "r"(a[1]), "r"(a[2]), "r"(a[3]), "r"(b0), "r"(b1));
}

__device__ __forceinline__ uint32_t pack_h2(float a, float b) {
    uint32_t r;
    asm("cvt.rn.f16x2.f32 %0, %1, %2;" : "=r"(r) : "f"(b), "f"(a));
    return r;
}

__device__ __forceinline__ void cp_async16(uint32_t saddr, const void* g) {
    asm volatile("cp.async.cg.shared.global [%0], [%1], 16;" :: "r"(saddr), "l"(g));
}
#define CP_COMMIT() asm volatile("cp.async.commit_group;" ::: "memory")
#define CP_WAIT0()  asm volatile("cp.async.wait_group 0;" ::: "memory")

// ---------------------------------------------------------------------------
// Kernel 0: W -> fp16, transposed to [n][k]; Wq pre-scaled by 384^-.5*log2e.
// ---------------------------------------------------------------------------
__global__ void wconv(const float* __restrict__ Wq, const float* __restrict__ Wk,
                      const float* __restrict__ Wv) {
    int idx = blockIdx.x * 256 + threadIdx.x;
    if (idx >= 3 * H_ * (EMB_ / 4)) return;
    int w  = idx / (H_ * (EMB_ / 4));
    int r  = idx % (H_ * (EMB_ / 4));
    int n  = r / (EMB_ / 4);
    int k4 = (r % (EMB_ / 4)) * 4;
    const float* W = (w == 0) ? Wq : (w == 1) ? Wk : Wv;
    const float s = (w == 0) ? 0.05103103630798287f * 1.4426950408889634f : 1.0f;
    float v0 = W[(k4 + 0) * H_ + n] * s;
    float v1 = W[(k4 + 1) * H_ + n] * s;
    float v2 = W[(k4 + 2) * H_ + n] * s;
    float v3 = W[(k4 + 3) * H_ + n] * s;
    uint2 p;
    p.x = pack_h2(v0, v1);
    p.y = pack_h2(v2, v3);
    *(uint2*)&g_wt[w][n][k4] = p;
}

// ---------------------------------------------------------------------------
// Kernel 1: QKV projection, fp16 mma, pipelined. 512 threads / 16 warps.
// Warp tile: 32 rows x 48 cols (4x4 warp grid over 128 x 192).
// Per ks: 2 A-ldsm + 3 B-ldsm for 12 mma (was 1+6 for 12).
// ---------------------------------------------------------------------------
#define SM_W0    32768
#define SMEM_SZ  (SM_W0 + 2*24576)

__device__ __forceinline__ void ldg_x(float4* xr, const float* __restrict__ xb,
                                      int k0, int tid) {
    #pragma unroll
    for (int it = 0; it < 4; it++) {
        int f = tid + it * 512;
        xr[it] = *(const float4*)&xb[(size_t)(f >> 4) * EMB_ + k0 + (f & 15) * 4];
    }
}

__device__ __forceinline__ void sts_x(const float4* xr, char* xs, int tid) {
    #pragma unroll
    for (int it = 0; it < 4; it++) {
        int f = tid + it * 512;
        uint32_t off = SW128((f >> 4) * 128 + (f & 15) * 8);
        uint2 p;
        p.x = pack_h2(xr[it].x, xr[it].y);
        p.y = pack_h2(xr[it].z, xr[it].w);
        *(uint2*)(xs + off) = p;
    }
}

__device__ __forceinline__ void cp_w(uint32_t wdst, int k0, int tid) {
    #pragma unroll
    for (int it = 0; it < 3; it++) {
        int f  = tid + it * 512;
        int w2 = f >> 9;
        int r  = f & 511;
        int n  = r >> 3;
        int q8 = r & 7;
        cp_async16(wdst + w2 * 8192 + SW128(n * 128 + q8 * 16),
                   &g_wt[w2][n][k0 + q8 * 8]);
    }
}

__global__ __launch_bounds__(512) void qkv_mm(const float* __restrict__ x)
{
    extern __shared__ char smem[];
    const uint32_t sb = smem_u32(smem);
    const int tid  = threadIdx.x;
    const int wid  = tid >> 5;
    const int lane = tid & 31;
    const int m0   = blockIdx.x * 128;
    const float* xb = x + (size_t)m0 * EMB_;

    const int wr = wid & 3;            // row group: rows wr*32 .. +32
    const int wc = wid >> 2;           // col group: cols wc*48 .. +48
    const int r_base = wr * 32;
    const int c_base = wc * 48;

    float acc[2][6][4] = {};

    const int lrow   = (lane & 7) + ((lane >> 3) & 1) * 8;
    const int a_colb = ((lane >> 4) & 1) * 16;
    const int b_n    = (lane >> 4) * 8 + (lane & 7);
    const int b_colb = ((lane >> 3) & 1) * 16;

    float4 xr[4];
    ldg_x(xr, xb, 0, tid);
    cp_w(sb + SM_W0, 0, tid);
    CP_COMMIT();

    #pragma unroll 1
    for (int c = 0; c < 6; c++) {
        const int st = c & 1;
        sts_x(xr, smem + st * 16384, tid);
        CP_WAIT0();
        __syncthreads();

        if (c < 5) {
            ldg_x(xr, xb, (c + 1) * 64, tid);
            cp_w(sb + SM_W0 + (st ^ 1) * 24576, (c + 1) * 64, tid);
            CP_COMMIT();
        }

        const uint32_t xs = sb + st * 16384;
        const uint32_t wbase = sb + SM_W0 + st * 24576;
        #pragma unroll
        for (int ks = 0; ks < 4; ks++) {
            uint32_t a0[4], a1[4];
            ldsm4(a0, xs + SW128((r_base + lrow)      * 128 + ks * 32 + a_colb));
            ldsm4(a1, xs + SW128((r_base + 16 + lrow) * 128 + ks * 32 + a_colb));
            #pragma unroll
            for (int np = 0; np < 3; np++) {
                const int colb = c_base + np * 16;
                const uint32_t wt = wbase + (colb >> 6) * 8192;
                const int nloc = colb & 63;
                uint32_t bb[4];
                ldsm4(bb, wt + SW128((nloc + b_n) * 128 + ks * 32 + b_colb));
                // bb[0]=n0-7/k0-7, bb[1]=n0-7/k8-15, bb[2]=n8-15/k0-7, bb[3]=n8-15/k8-15
                mma16816h(acc[0][2*np],   a0, bb[0], bb[1]);
                mma16816h(acc[0][2*np+1], a0, bb[2], bb[3]);
                mma16816h(acc[1][2*np],   a1, bb[0], bb[1]);
                mma16816h(acc[1][2*np+1], a1, bb[2], bb[3]);
            }
        }
    }

    // epilogue: pack fp16, store uint32 per 2 cols
    const int g  = lane >> 2;
    const int c2 = (lane & 3) * 2;
    #pragma unroll
    for (int rg = 0; rg < 2; rg++) {
        const int r0 = m0 + r_base + rg * 16 + g;
        #pragma unroll
        for (int nt = 0; nt < 6; nt++) {
            int col = c_base + nt * 8 + c2;
            int w2  = col >> 6;
            int n   = col & 63;
            *(uint32_t*)&g_qkv[w2][(size_t)r0 * H_ + n] =
                pack_h2(acc[rg][nt][0], acc[rg][nt][1]);
            *(uint32_t*)&g_qkv[w2][(size_t)(r0 + 8) * H_ + n] =
                pack_h2(acc[rg][nt][2], acc[rg][nt][3]);
        }
    }
}

// ---------------------------------------------------------------------------
// Kernel 2: fp16 tensor-core causal attention.
// Q/K/V staged via cp.async; Q fragments via ldsm (coalesced).
// smem: Q 32K at 0, K 32K at 32768, V 32K at 65536.  96 KB -> 2 CTAs/SM.
// ---------------------------------------------------------------------------
#define ATTN_SMEM 98304

__global__ __launch_bounds__(256) void attn_tc(float* __restrict__ out)
{
    extern __shared__ char smem[];
    const uint32_t sb = smem_u32(smem);
    const int b    = blockIdx.x;
    const int tid  = threadIdx.x;
    const int wid  = tid >> 5;
    const int lane = tid & 31;

    const __half* qh = g_qkv[0] + (size_t)b * T_ * H_;
    const __half* kh = g_qkv[1] + (size_t)b * T_ * H_;
    const __half* vh = g_qkv[2] + (size_t)b * T_ * H_;

    // Stage Q, K, V via cp.async: 256 rows x 8 x 16B chunks each.
    #pragma unroll
    for (int it = 0; it < 8; it++) {
        int f  = tid + it * 256;     // 0..2047
        int j  = f >> 3;
        int q8 = f & 7;
        uint32_t off = SW128(j * 128 + q8 * 16);
        size_t  gof = (size_t)j * H_ + q8 * 8;
        cp_async16(sb + off,         &qh[gof]);
        cp_async16(sb + 32768 + off, &kh[gof]);
        cp_async16(sb + 65536 + off, &vh[gof]);
    }
    CP_COMMIT();
    CP_WAIT0();
    __syncthreads();

    const int g  = lane >> 2;
    const int c4 = lane & 3;
    const int lrow  = (lane & 7) + ((lane >> 3) & 1) * 8;
    const int lcolh = ((lane >> 4) & 1) * 16;

    const uint32_t qbase = sb;
    const uint32_t kbase = sb + 32768;
    const uint32_t vbase = sb + 65536;

    #pragma unroll 1
    for (int half = 0; half < 2; half++) {
        const int tt = (half == 0) ? wid : 15 - wid;
        const int r0 = tt * 16;

        // Q fragments via ldsm (A-operand layout)
        uint32_t qf[4][4];
        #pragma unroll
        for (int kc = 0; kc < 4; kc++)
            ldsm4(qf[kc], qbase + SW128((r0 + lrow) * 128 + kc * 32 + lcolh));

        float oacc[8][4] = {};
        float sum0 = 0.0f, sum1 = 0.0f;
        const int nb = (r0 + 47) >> 5;

        #pragma unroll 1
        for (int blk = 0; blk < nb; blk++) {
            const int s0 = blk * 32;
            float sacc[4][4] = {};

            // ---- S = Q K^T ----
            #pragma unroll
            for (int kc = 0; kc < 4; kc++) {
                uint32_t bh[8];
                #pragma unroll
                for (int grp = 0; grp < 2; grp++) {
                    uint32_t off = SW128((s0 + grp * 16 + lrow) * 128 + kc * 32 + lcolh);
                    ldsm4(&bh[grp * 4], kbase + off);
                }
                #pragma unroll
                for (int nt = 0; nt < 4; nt++) {
                    const int base = (nt >> 1) * 4;
                    mma16816h(sacc[nt], qf[kc],
                              bh[base + (nt & 1)], bh[base + (nt & 1) + 2]);
                }
            }

            // ---- exp2 + causal mask + rowsum ----
            const bool last = (blk == nb - 1);
            float p[4][4];
            #pragma unroll
            for (int nt = 0; nt < 4; nt++) {
                #pragma unroll
                for (int rr = 0; rr < 4; rr++) {
                    int j = s0 + nt * 8 + 2 * c4 + (rr & 1);
                    int t = r0 + g + (rr >> 1) * 8;
                    float e = (!last || j <= t) ? exp2f(sacc[nt][rr]) : 0.0f;
                    p[nt][rr] = e;
                    if (rr < 2) sum0 += e; else sum1 += e;
                }
            }

            // ---- P fragments, fp16 ----
            uint32_t pf[2][4];
            #pragma unroll
            for (int kc2 = 0; kc2 < 2; kc2++) {
                const float* p0 = p[2 * kc2];
                const float* p1 = p[2 * kc2 + 1];
                pf[kc2][0] = pack_h2(p0[0], p0[1]);
                pf[kc2][1] = pack_h2(p0[2], p0[3]);
                pf[kc2][2] = pack_h2(p1[0], p1[1]);
                pf[kc2][3] = pack_h2(p1[2], p1[3]);
            }

            // ---- O += P V ----
            #pragma unroll
            for (int kc2 = 0; kc2 < 2; kc2++) {
                #pragma unroll
                for (int np = 0; np < 4; np++) {
                    uint32_t off = SW128((s0 + kc2 * 16 + lrow) * 128 + np * 32 + lcolh);
                    uint32_t vb[4];
                    ldsm4t(vb, vbase + off);
                    mma16816h(oacc[2*np],   pf[kc2], vb[0], vb[1]);
                    mma16816h(oacc[2*np+1], pf[kc2], vb[2], vb[3]);
                }
            }
        }

        // ---- rowsum reduce, scale, store ----
        sum0 += __shfl_xor_sync(0xffffffffu, sum0, 1);
        sum0 += __shfl_xor_sync(0xffffffffu, sum0, 2);
        sum1 += __shfl_xor_sync(0xffffffffu, sum1, 1);
        sum1 += __shfl_xor_sync(0xffffffffu, sum1, 2);
        const float inv0 = 1.0f / sum0;
        const float inv1 = 1.0f / sum1;

        float* orow0 = out + ((size_t)b * T_ + r0 + g) * H_;
        float* orow1 = out + ((size_t)b * T_ + r0 + g + 8) * H_;
        #pragma unroll
        for (int nt = 0; nt < 8; nt++) {
            int n = nt * 8 + 2 * c4;
            *(float2*)&orow0[n] = make_float2(oacc[nt][0] * inv0, oacc[nt][1] * inv0);
            *(float2*)&orow1[n] = make_float2(oacc[nt][2] * inv1, oacc[nt][3] * inv1);
        }
    }
}

// ---------------------------------------------------------------------------
extern "C" void kernel_launch(void* const* d_in, const int* in_sizes, int n_in,
                              void* d_out, int out_size)
{
    const float* x  = (const float*)d_in[0];
    const float* Wq = (const float*)d_in[1];
    const float* Wk = (const float*)d_in[2];
    const float* Wv = (const float*)d_in[3];
    float* out = (float*)d_out;
    (void)in_sizes; (void)n_in; (void)out_size;

    wconv<<<(3 * H_ * (EMB_ / 4) + 255) / 256, 256>>>(Wq, Wk, Wv);

    cudaFuncSetAttribute(qkv_mm, cudaFuncAttributeMaxDynamicSharedMemorySize, SMEM_SZ);
    qkv_mm<<<M_ / 128, 512, SMEM_SZ>>>(x);

    cudaFuncSetAttribute(attn_tc, cudaFuncAttributeMaxDynamicSharedMemorySize, ATTN_SMEM);
    attn_tc<<<B_, 256, ATTN_SMEM>>>(out);
}